// round 2
// baseline (speedup 1.0000x reference)
#include <cuda_runtime.h>

// ============================================================================
// FullyConnectedSteerableGeometricProductLayer  (Cl(3,0), 8 blades)
// B=2048, N_IN=N_OUT=512, 20 paths, 64 Cayley edges.
//
// Restructured:
//   XT[i][b][n]   = x[b][n][i]                          (transpose)
//   XR[i][b][m]   = sum_n XT[i][b][n] * w_right[m][n][g(i)]   (8 GEMMs, grid.z)
//   XR gated by grade norms (elementwise)
//   Q  (per output grade): 44 channels q[b,j][p,n] from 64 edges (elementwise)
//   OUT8[i] = left GEMM (w_left, +bias on blade0)  then  += bilinear GEMMs
//   out = OUT8 / sqrt(2), interleaved
// ============================================================================

#define BDIM   2048
#define NIN    512
#define NOUT   512
#define PLANE  (BDIM * NIN)          // 1048576
#define WSLICE (512 * 512)           // 262144

// grade-grouped path order (global path ids, argwhere order):
//  g0: (0,0,0)(1,0,1)(2,0,2)(3,0,3) -> 0,4,10,16
//  g1: (0,1,1)(1,1,0)(1,1,2)(2,1,1)(2,1,3)(3,1,2) -> 1,5,6,11,12,17
//  g2: (0,2,2)(1,2,1)(1,2,3)(2,2,0)(2,2,2)(3,2,1) -> 2,7,8,13,14,18
//  g3: (0,3,3)(1,3,2)(2,3,1)(3,3,0) -> 3,9,15,19
__constant__ int c_porder[20] = {0,4,10,16, 1,5,6,11,12,17, 2,7,8,13,14,18, 3,9,15,19};
__constant__ int c_grade[8]   = {0,1,1,1,2,2,2,3};

// Q buffer layout (row-major [M_g x K_g] per grade, concatenated):
//  g0: M=2048 K=2048  off 0
//  g1: M=6144 K=3072  off 4194304
//  g2: M=6144 K=3072  off 23068672
//  g3: M=2048 K=2048  off 41943040   total 46137344 floats
#define QOFF0 0
#define QOFF1 4194304
#define QOFF2 23068672
#define QOFF3 41943040
#define QTOT  46137344

__device__ float g_XT  [8 * PLANE];
__device__ float g_XR  [8 * PLANE];
__device__ float g_OUT8[8 * PLANE];
__device__ float g_WT  [20 * WSLICE];
__device__ float g_WRT [4 * WSLICE];
__device__ float g_WLT [4 * WSLICE];
__device__ float g_Q   [QTOT];

// ---------------------------------------------------------------------------
// x (b,n,8) -> 8 planes XT[i][b*512+n]
__global__ void transpose_x_kernel(const float* __restrict__ x) {
    int idx = blockIdx.x * 256 + threadIdx.x;          // b*512+n
    const float4* x4 = (const float4*)x;
    float4 a = x4[idx * 2];
    float4 b = x4[idx * 2 + 1];
    g_XT[0 * PLANE + idx] = a.x;
    g_XT[1 * PLANE + idx] = a.y;
    g_XT[2 * PLANE + idx] = a.z;
    g_XT[3 * PLANE + idx] = a.w;
    g_XT[4 * PLANE + idx] = b.x;
    g_XT[5 * PLANE + idx] = b.y;
    g_XT[6 * PLANE + idx] = b.z;
    g_XT[7 * PLANE + idx] = b.w;
}

// weight (m,n,20) -> WT[kb][n][m];  w_right/(w_left) (m,n,4) -> WRT/WLT[g][n][m]
__global__ void prep_weights_kernel(const float* __restrict__ weight,
                                    const float* __restrict__ w_right,
                                    const float* __restrict__ w_left) {
    int idx = blockIdx.x * 256 + threadIdx.x;
    const int WT_N = 20 * WSLICE;
    const int W4_N = 4 * WSLICE;
    if (idx < WT_N) {
        int kb  = idx >> 18;
        int rem = idx & (WSLICE - 1);
        int n = rem >> 9;
        int m = rem & 511;
        g_WT[idx] = weight[(m * 512 + n) * 20 + c_porder[kb]];
    } else if (idx < WT_N + W4_N) {
        int t = idx - WT_N;
        int g = t >> 18;
        int rem = t & (WSLICE - 1);
        int n = rem >> 9;
        int m = rem & 511;
        g_WRT[t] = w_right[(m * 512 + n) * 4 + g];
    } else if (idx < WT_N + 2 * W4_N) {
        int t = idx - WT_N - W4_N;
        int g = t >> 18;
        int rem = t & (WSLICE - 1);
        int n = rem >> 9;
        int m = rem & 511;
        g_WLT[t] = w_left[(m * 512 + n) * 4 + g];
    }
}

// ---------------------------------------------------------------------------
// Shared SGEMM tile core: C[128x128] of A[MxK] (row-major, lda=K) @ B[Kx512]
// (row-major, ldb=512). 256 threads, 8x8 per-thread microtile, BK=8.
__device__ __forceinline__ void sgemm_tile(const float* __restrict__ A,
                                           const float* __restrict__ B,
                                           int K, int row0, int col0,
                                           float acc[8][8]) {
    __shared__ float As[8][128];
    __shared__ float Bs[8][128];
    int tid  = threadIdx.x;
    int arow = tid >> 1;
    int acol = (tid & 1) * 4;
    int brow = tid >> 5;
    int bcol = (tid & 31) * 4;
    int tr   = tid >> 4;
    int tc   = tid & 15;

    const float* Aptr = A + (long long)(row0 + arow) * K + acol;
    const float* Bptr = B + brow * 512 + col0 + bcol;

    for (int kt = 0; kt < K; kt += 8) {
        float4 a4 = *(const float4*)(Aptr + kt);
        float4 b4 = *(const float4*)(Bptr + (long long)kt * 512);
        As[acol + 0][arow] = a4.x;
        As[acol + 1][arow] = a4.y;
        As[acol + 2][arow] = a4.z;
        As[acol + 3][arow] = a4.w;
        *(float4*)&Bs[brow][bcol] = b4;
        __syncthreads();
#pragma unroll
        for (int k = 0; k < 8; k++) {
            float a[8], b[8];
            *(float4*)(a)     = *(const float4*)&As[k][tr * 8];
            *(float4*)(a + 4) = *(const float4*)&As[k][tr * 8 + 4];
            *(float4*)(b)     = *(const float4*)&Bs[k][tc * 8];
            *(float4*)(b + 4) = *(const float4*)&Bs[k][tc * 8 + 4];
#pragma unroll
            for (int i = 0; i < 8; i++)
#pragma unroll
                for (int j = 0; j < 8; j++)
                    acc[i][j] += a[i] * b[j];
        }
        __syncthreads();
    }
}

// XR / LEFT: one launch, grid (4, 16, 8). mode 0: W=WRT C=XR; mode 1: W=WLT C=OUT8 (+bias z==0)
__global__ void __launch_bounds__(256, 2)
gemm_planes_kernel(const float* __restrict__ bias, int mode) {
    int z = blockIdx.z;
    int g = c_grade[z];
    const float* A = &g_XT[z * PLANE];
    const float* B = (mode == 0) ? &g_WRT[g * WSLICE] : &g_WLT[g * WSLICE];
    float*       C = (mode == 0) ? &g_XR[z * PLANE]   : &g_OUT8[z * PLANE];

    int row0 = blockIdx.y * 128;
    int col0 = blockIdx.x * 128;
    float acc[8][8] = {};
    sgemm_tile(A, B, NIN, row0, col0, acc);

    int tr = threadIdx.x >> 4;
    int tc = threadIdx.x & 15;
    bool addb = (mode == 1) && (z == 0);
    int cbase = col0 + tc * 8;
#pragma unroll
    for (int i = 0; i < 8; i++) {
        int r = row0 + tr * 8 + i;
        float v[8];
#pragma unroll
        for (int j = 0; j < 8; j++) {
            v[j] = acc[i][j];
            if (addb) v[j] += bias[cbase + j];
        }
        float* dst = C + r * 512 + cbase;
        *(float4*)(dst)     = make_float4(v[0], v[1], v[2], v[3]);
        *(float4*)(dst + 4) = make_float4(v[4], v[5], v[6], v[7]);
    }
}

// Bilinear GEMMs: grid (4, 128). yb<16:g0, <64:g1, <112:g2, else g3. Accumulates into OUT8.
__global__ void __launch_bounds__(256, 2)
gemm_bilinear_kernel() {
    int yb = blockIdx.y;
    int g, rb;
    if      (yb < 16)  { g = 0; rb = yb; }
    else if (yb < 64)  { g = 1; rb = yb - 16; }
    else if (yb < 112) { g = 2; rb = yb - 64; }
    else               { g = 3; rb = yb - 112; }

    int K, s, pb;
    long long qoff;
    int koff;
    if (g == 0)      { K = 2048; s = 1; pb = 0; qoff = QOFF0; koff = 0; }
    else if (g == 1) { K = 3072; s = 3; pb = 1; qoff = QOFF1; koff = 4  * WSLICE; }
    else if (g == 2) { K = 3072; s = 3; pb = 4; qoff = QOFF2; koff = 10 * WSLICE; }
    else             { K = 2048; s = 1; pb = 7; qoff = QOFF3; koff = 16 * WSLICE; }

    const float* A = &g_Q[qoff];
    const float* B = &g_WT[koff];
    int row0 = rb * 128;
    int col0 = blockIdx.x * 128;
    float acc[8][8] = {};
    sgemm_tile(A, B, K, row0, col0, acc);

    int tr = threadIdx.x >> 4;
    int tc = threadIdx.x & 15;
    int cbase = col0 + tc * 8;
#pragma unroll
    for (int i = 0; i < 8; i++) {
        int r = row0 + tr * 8 + i;
        int bb, j;
        if (s == 1) { bb = r; j = 0; }
        else        { bb = r / 3; j = r - bb * 3; }
        float* dst = &g_OUT8[(long long)(pb + j) * PLANE + bb * 512 + cbase];
        float4 lo = *(float4*)(dst);
        float4 hi = *(float4*)(dst + 4);
        lo.x += acc[i][0]; lo.y += acc[i][1]; lo.z += acc[i][2]; lo.w += acc[i][3];
        hi.x += acc[i][4]; hi.y += acc[i][5]; hi.z += acc[i][6]; hi.w += acc[i][7];
        *(float4*)(dst)     = lo;
        *(float4*)(dst + 4) = hi;
    }
}

// ---------------------------------------------------------------------------
// Grade-norm gating of XR (in place). norm_a: (1, 512, 4)
__global__ void norm_scale_kernel(const float* __restrict__ norm_a) {
    int idx = blockIdx.x * 256 + threadIdx.x;   // b*512 + m
    int m = idx & 511;
    float r[8];
#pragma unroll
    for (int i = 0; i < 8; i++) r[i] = g_XR[i * PLANE + idx];

    float n0 = sqrtf(r[0] * r[0]);
    float n1 = sqrtf(r[1] * r[1] + r[2] * r[2] + r[3] * r[3]);
    float n2 = sqrtf(r[4] * r[4] + r[5] * r[5] + r[6] * r[6]);
    float n3 = sqrtf(r[7] * r[7]);

    float f[4];
    float nn[4] = {n0, n1, n2, n3};
#pragma unroll
    for (int gg = 0; gg < 4; gg++) {
        float a = norm_a[m * 4 + gg];
        float sg = 1.0f / (1.0f + expf(-a));
        f[gg] = sg * (nn[gg] - 1.0f) + 1.0f + 1e-6f;
    }
    r[0] /= f[0];
    r[1] /= f[1]; r[2] /= f[1]; r[3] /= f[1];
    r[4] /= f[2]; r[5] /= f[2]; r[6] /= f[2];
    r[7] /= f[3];
#pragma unroll
    for (int i = 0; i < 8; i++) g_XR[i * PLANE + idx] = r[i];
}

// Build the 44 Q channels from the 64 Cayley edges.
__global__ void q_fill_kernel(const float* __restrict__ x) {
    int idx = blockIdx.x * 256 + threadIdx.x;   // b*512 + n
    int b = idx >> 9;
    int n = idx & 511;

    const float4* x4 = (const float4*)x;
    float4 xa = x4[idx * 2];
    float4 xb = x4[idx * 2 + 1];
    float x0 = xa.x, x1 = xa.y, x2 = xa.z, x3 = xa.w;
    float x4v = xb.x, x5 = xb.y, x6 = xb.z, x7 = xb.w;

    float r0 = g_XR[0 * PLANE + idx], r1 = g_XR[1 * PLANE + idx];
    float r2 = g_XR[2 * PLANE + idx], r3 = g_XR[3 * PLANE + idx];
    float r4 = g_XR[4 * PLANE + idx], r5 = g_XR[5 * PLANE + idx];
    float r6 = g_XR[6 * PLANE + idx], r7 = g_XR[7 * PLANE + idx];

    // grade 0 (blade 0): K=2048, paths (0,0,0)(1,0,1)(2,0,2)(3,0,3)
    {
        float* q = &g_Q[QOFF0 + (long long)b * 2048 + n];
        q[0]    = x0 * r0;
        q[512]  = x1 * r1 + x2 * r2 + x3 * r3;
        q[1024] = -(x4v * r4 + x5 * r5 + x6 * r6);
        q[1536] = -(x7 * r7);
    }
    // grade 1 (blades 1,2,3): K=3072, paths (0,1,1)(1,1,0)(1,1,2)(2,1,1)(2,1,3)(3,1,2)
    {
        float* q = &g_Q[QOFF1 + (long long)(b * 3) * 3072 + n];
        // j=0 -> blade e1
        q[0]    = x0 * r1;
        q[512]  = x1 * r0;
        q[1024] = -x2 * r4 - x3 * r5;
        q[1536] = x4v * r2 + x5 * r3;
        q[2048] = -x6 * r7;
        q[2560] = -x7 * r6;
        // j=1 -> blade e2
        q[3072 + 0]    = x0 * r2;
        q[3072 + 512]  = x2 * r0;
        q[3072 + 1024] = x1 * r4 - x3 * r6;
        q[3072 + 1536] = -x4v * r1 + x6 * r3;
        q[3072 + 2048] = x5 * r7;
        q[3072 + 2560] = x7 * r5;
        // j=2 -> blade e3
        q[6144 + 0]    = x0 * r3;
        q[6144 + 512]  = x3 * r0;
        q[6144 + 1024] = x1 * r5 + x2 * r6;
        q[6144 + 1536] = -x5 * r1 - x6 * r2;
        q[6144 + 2048] = -x4v * r7;
        q[6144 + 2560] = -x7 * r4;
    }
    // grade 2 (blades e12,e13,e23): paths (0,2,2)(1,2,1)(1,2,3)(2,2,0)(2,2,2)(3,2,1)
    {
        float* q = &g_Q[QOFF2 + (long long)(b * 3) * 3072 + n];
        // j=0 -> e12
        q[0]    = x0 * r4;
        q[512]  = x1 * r2 - x2 * r1;
        q[1024] = x3 * r7;
        q[1536] = x4v * r0;
        q[2048] = -x5 * r6 + x6 * r5;
        q[2560] = x7 * r3;
        // j=1 -> e13
        q[3072 + 0]    = x0 * r5;
        q[3072 + 512]  = x1 * r3 - x3 * r1;
        q[3072 + 1024] = -x2 * r7;
        q[3072 + 1536] = x5 * r0;
        q[3072 + 2048] = x4v * r6 - x6 * r4;
        q[3072 + 2560] = -x7 * r2;
        // j=2 -> e23
        q[6144 + 0]    = x0 * r6;
        q[6144 + 512]  = x2 * r3 - x3 * r2;
        q[6144 + 1024] = x1 * r7;
        q[6144 + 1536] = x6 * r0;
        q[6144 + 2048] = -x4v * r5 + x5 * r4;
        q[6144 + 2560] = x7 * r1;
    }
    // grade 3 (blade e123): paths (0,3,3)(1,3,2)(2,3,1)(3,3,0)
    {
        float* q = &g_Q[QOFF3 + (long long)b * 2048 + n];
        q[0]    = x0 * r7;
        q[512]  = x1 * r6 - x2 * r5 + x3 * r4;
        q[1024] = x4v * r3 - x5 * r2 + x6 * r1;
        q[1536] = x7 * r0;
    }
}

// OUT8 planes -> interleaved output, * 1/sqrt(2)
__global__ void merge_out_kernel(float* __restrict__ out) {
    int idx = blockIdx.x * 256 + threadIdx.x;   // b*512 + m
    const float s = 0.70710678118654752440f;
    float4 lo, hi;
    lo.x = g_OUT8[0 * PLANE + idx] * s;
    lo.y = g_OUT8[1 * PLANE + idx] * s;
    lo.z = g_OUT8[2 * PLANE + idx] * s;
    lo.w = g_OUT8[3 * PLANE + idx] * s;
    hi.x = g_OUT8[4 * PLANE + idx] * s;
    hi.y = g_OUT8[5 * PLANE + idx] * s;
    hi.z = g_OUT8[6 * PLANE + idx] * s;
    hi.w = g_OUT8[7 * PLANE + idx] * s;
    float4* o4 = (float4*)out;
    o4[idx * 2]     = lo;
    o4[idx * 2 + 1] = hi;
}

// ---------------------------------------------------------------------------
extern "C" void kernel_launch(void* const* d_in, const int* in_sizes, int n_in,
                              void* d_out, int out_size) {
    const float* x       = (const float*)d_in[0];
    const float* weight  = (const float*)d_in[1];
    const float* w_right = (const float*)d_in[2];
    const float* w_left  = (const float*)d_in[3];
    const float* b_left  = (const float*)d_in[4];
    const float* norm_a  = (const float*)d_in[5];
    float* out = (float*)d_out;

    transpose_x_kernel<<<PLANE / 256, 256>>>(x);
    prep_weights_kernel<<<(28 * WSLICE) / 256, 256>>>(weight, w_right, w_left);

    dim3 gp(4, 16, 8);
    gemm_planes_kernel<<<gp, 256>>>(b_left, 0);          // XR = x @ w_right
    norm_scale_kernel<<<PLANE / 256, 256>>>(norm_a);     // gate XR
    q_fill_kernel<<<PLANE / 256, 256>>>(x);              // 44 channels
    gemm_planes_kernel<<<gp, 256>>>(b_left, 1);          // OUT8 = left (+bias)
    gemm_bilinear_kernel<<<dim3(4, 128, 1), 256>>>();    // OUT8 += bilinear
    merge_out_kernel<<<PLANE / 256, 256>>>(out);
}

// round 5
// speedup vs baseline: 2.2127x; 2.2127x over previous
#include <cuda_runtime.h>
#include <cuda_bf16.h>
#include <cstdint>

// ============================================================================
// Cl(3,0) steerable geometric product layer — baseline-PTX tensor cores.
// mma.sync.m16n8k16 bf16 (split hi/lo, 3 products) + ldmatrix + cp.async.
// Dataflow identical to the passing fp32 version:
//   XR[i] = XT[i] @ WR[g(i)]   (8 GEMMs)        OUT8[i] = XT[i] @ WL[g(i)] (+bias)
//   Q channels (44) from gated XR x x           OUT8 += Q @ WB  (4 grade GEMMs)
//   out = OUT8 / sqrt(2)
// ============================================================================

#define BDIM   2048
#define NIN    512
#define PLANE  (BDIM * NIN)          // 1048576
#define WSLICE (512 * 512)           // 262144

#define QOFF0 0
#define QOFF1 4194304
#define QOFF2 23068672
#define QOFF3 41943040
#define QTOT  46137344

#define WBOFF0 0
#define WBOFF1 1048576
#define WBOFF2 2621440
#define WBOFF3 4194304
#define WBTOT  5242880

__constant__ int c_porder[20] = {0,4,10,16, 1,5,6,11,12,17, 2,7,8,13,14,18, 3,9,15,19};
__constant__ int c_grade[8]   = {0,1,1,1,2,2,2,3};
__constant__ int c_kb_base[20] = {
    WBOFF0+0, WBOFF0+512, WBOFF0+1024, WBOFF0+1536,
    WBOFF1+0, WBOFF1+512, WBOFF1+1024, WBOFF1+1536, WBOFF1+2048, WBOFF1+2560,
    WBOFF2+0, WBOFF2+512, WBOFF2+1024, WBOFF2+1536, WBOFF2+2048, WBOFF2+2560,
    WBOFF3+0, WBOFF3+512, WBOFF3+1024, WBOFF3+1536};
__constant__ int c_kb_K[20] = {2048,2048,2048,2048, 3072,3072,3072,3072,3072,3072,
                               3072,3072,3072,3072,3072,3072, 2048,2048,2048,2048};

__device__ __align__(256) __nv_bfloat16 g_XTh[8 * PLANE];
__device__ __align__(256) __nv_bfloat16 g_XTl[8 * PLANE];
__device__ __align__(256) __nv_bfloat16 g_WRh[4 * WSLICE];
__device__ __align__(256) __nv_bfloat16 g_WRl[4 * WSLICE];
__device__ __align__(256) __nv_bfloat16 g_WLh[4 * WSLICE];
__device__ __align__(256) __nv_bfloat16 g_WLl[4 * WSLICE];
__device__ __align__(256) __nv_bfloat16 g_WBh[WBTOT];
__device__ __align__(256) __nv_bfloat16 g_WBl[WBTOT];
__device__ __align__(256) __nv_bfloat16 g_Qh[QTOT];
__device__ __align__(256) __nv_bfloat16 g_Ql[QTOT];
__device__ float g_XR  [8 * PLANE];
__device__ float g_OUT8[8 * PLANE];

// ---------------------------------------------------------------------------
__device__ __forceinline__ uint32_t s2u(const void* p) {
    return (uint32_t)__cvta_generic_to_shared(p);
}
__device__ __forceinline__ void cp16(uint32_t dst, const void* src) {
    asm volatile("cp.async.cg.shared.global [%0], [%1], 16;\n" :: "r"(dst), "l"(src));
}
#define CP_COMMIT() asm volatile("cp.async.commit_group;\n" ::: "memory")
#define CP_WAIT1()  asm volatile("cp.async.wait_group 1;\n" ::: "memory")
#define CP_WAIT0()  asm volatile("cp.async.wait_group 0;\n" ::: "memory")

__device__ __forceinline__ void ldsm4(uint32_t* r, uint32_t addr) {
    asm volatile("ldmatrix.sync.aligned.m8n8.x4.shared.b16 {%0,%1,%2,%3}, [%4];"
                 : "=r"(r[0]), "=r"(r[1]), "=r"(r[2]), "=r"(r[3]) : "r"(addr));
}
__device__ __forceinline__ void mma_bf16(float* c, const uint32_t* a,
                                         uint32_t b0, uint32_t b1) {
    asm volatile(
        "mma.sync.aligned.m16n8k16.row.col.f32.bf16.bf16.f32 "
        "{%0,%1,%2,%3}, {%4,%5,%6,%7}, {%8,%9}, {%0,%1,%2,%3};"
        : "+f"(c[0]), "+f"(c[1]), "+f"(c[2]), "+f"(c[3])
        : "r"(a[0]), "r"(a[1]), "r"(a[2]), "r"(a[3]), "r"(b0), "r"(b1));
}

#define SWZ(o) ((o) ^ (((o) >> 3) & 0x70))

// SMEM: 2 stages x (A 128x64 bf16 = 16KB, B 128x64 bf16 = 16KB) = 64KB
#define STAGE_BYTES 32768u
#define SMEM_BYTES  65536

// Load one K=64 chunk: A rows [row0,row0+128), B rows [col0,col0+128), both
// row-major with stride Ka (bf16). 256 threads, 8 cp16 each.
__device__ __forceinline__ void load_chunk(
    uint32_t sb, int buf,
    const __nv_bfloat16* __restrict__ A, const __nv_bfloat16* __restrict__ B,
    int row0, int col0, int Ka, int kt, int tid)
{
    uint32_t st = sb + buf * STAGE_BYTES;
#pragma unroll
    for (int i = 0; i < 8; i++) {
        int idx = i * 256 + tid;          // 0..2047
        int r   = idx >> 3;               // 0..255
        int c16 = idx & 7;
        if (r < 128) {
            uint32_t so = SWZ((uint32_t)((r << 7) + (c16 << 4)));
            cp16(st + so, A + (size_t)(row0 + r) * Ka + kt + (c16 << 3));
        } else {
            int lr = r - 128;
            uint32_t so = SWZ((uint32_t)((lr << 7) + (c16 << 4)));
            cp16(st + 16384u + so, B + (size_t)(col0 + lr) * Ka + kt + (c16 << 3));
        }
    }
}

// ---------------------------------------------------------------------------
// Unified GEMM kernel, CTA tile 128x128, 8 warps (4 M x 2 N), warp tile 32x64.
// mode 0: grid (4,16,16)  z<8: XR = XT@WR  ; z>=8: OUT8 = XT@WL (+bias z==0)
// mode 2: grid (4,128,1)  OUT8 += Q@WB (bilinear, grade-grouped rows)
// Split-bf16: 3 K-passes (Ah*Bh, Al*Bh, Ah*Bl), fp32 accumulate.
// ---------------------------------------------------------------------------
__global__ void __launch_bounds__(256, 1)
gemm_mma(int mode, const float* __restrict__ bias) {
    extern __shared__ __align__(1024) char smem[];
    uint32_t sb = s2u(smem);
    int tid = threadIdx.x, lane = tid & 31, wid = tid >> 5;

    const __nv_bfloat16 *Ah, *Al, *Bh, *Bl;
    int Ka, row0, col0;
    int z = 0, is_left = 0, pb = 0, s = 1;

    if (mode == 0) {
        int zz = blockIdx.z; z = zz & 7; is_left = zz >> 3;
        int g = c_grade[z];
        row0 = blockIdx.y * 128; col0 = blockIdx.x * 128;
        Ka = 512;
        Ah = g_XTh + (size_t)z * PLANE; Al = g_XTl + (size_t)z * PLANE;
        if (is_left) { Bh = g_WLh + (size_t)g * WSLICE; Bl = g_WLl + (size_t)g * WSLICE; }
        else         { Bh = g_WRh + (size_t)g * WSLICE; Bl = g_WRl + (size_t)g * WSLICE; }
    } else {
        int yb = blockIdx.y, g, rb;
        if      (yb < 16)  { g = 0; rb = yb; }
        else if (yb < 64)  { g = 1; rb = yb - 16; }
        else if (yb < 112) { g = 2; rb = yb - 64; }
        else               { g = 3; rb = yb - 112; }
        size_t qo; int wo;
        if      (g == 0) { Ka = 2048; s = 1; pb = 0; qo = QOFF0; wo = WBOFF0; }
        else if (g == 1) { Ka = 3072; s = 3; pb = 1; qo = QOFF1; wo = WBOFF1; }
        else if (g == 2) { Ka = 3072; s = 3; pb = 4; qo = QOFF2; wo = WBOFF2; }
        else             { Ka = 2048; s = 1; pb = 7; qo = QOFF3; wo = WBOFF3; }
        row0 = rb * 128; col0 = blockIdx.x * 128;
        Ah = g_Qh + qo; Al = g_Ql + qo;
        Bh = g_WBh + wo; Bl = g_WBl + wo;
    }

    const __nv_bfloat16* pA[3] = {Ah, Al, Ah};
    const __nv_bfloat16* pB[3] = {Bh, Bh, Bl};
    int nch = Ka >> 6;
    int tc  = 3 * nch;

    // lane-constant ldmatrix address pieces
    int a_row = (wid & 3) * 32 + (lane & 15);          // + mt*16
    int b_row = (wid >> 2) * 64 + (lane & 7) + ((lane >> 4) << 3);  // + bt*16
    uint32_t a_colp = (uint32_t)((lane >> 4) << 4);
    uint32_t b_colp = (uint32_t)(((lane >> 3) & 1) << 4);
    uint32_t xmask  = (uint32_t)((lane & 7) << 4);

    float acc[2][8][4];
#pragma unroll
    for (int mt = 0; mt < 2; mt++)
#pragma unroll
        for (int nt = 0; nt < 8; nt++)
#pragma unroll
            for (int q = 0; q < 4; q++) acc[mt][nt][q] = 0.0f;

    load_chunk(sb, 0, pA[0], pB[0], row0, col0, Ka, 0, tid);
    CP_COMMIT();

    for (int c = 0; c < tc; c++) {
        int buf = c & 1;
        if (c + 1 < tc) {
            int cn = c + 1;
            int pass = cn / nch, kk = cn - pass * nch;
            load_chunk(sb, buf ^ 1, pA[pass], pB[pass], row0, col0, Ka, kk << 6, tid);
            CP_COMMIT();
            CP_WAIT1();
        } else {
            CP_WAIT0();
        }
        __syncthreads();

        uint32_t sA = sb + buf * STAGE_BYTES;
        uint32_t sB = sA + 16384u;
#pragma unroll
        for (int ks = 0; ks < 4; ks++) {
            uint32_t acol = ((uint32_t)(ks << 5) | a_colp) ^ xmask;
            uint32_t bcol = ((uint32_t)(ks << 5) | b_colp) ^ xmask;
            uint32_t af[2][4], bf[4][4];
#pragma unroll
            for (int mt = 0; mt < 2; mt++)
                ldsm4(af[mt], sA + (uint32_t)((a_row + mt * 16) << 7) + acol);
#pragma unroll
            for (int bt = 0; bt < 4; bt++)
                ldsm4(bf[bt], sB + (uint32_t)((b_row + bt * 16) << 7) + bcol);
#pragma unroll
            for (int mt = 0; mt < 2; mt++)
#pragma unroll
                for (int nt = 0; nt < 8; nt++)
                    mma_bf16(acc[mt][nt], af[mt], bf[nt >> 1][(nt & 1) * 2],
                             bf[nt >> 1][(nt & 1) * 2 + 1]);
        }
        __syncthreads();
    }

    // ---------------- epilogue ----------------
    int gr = row0 + (wid & 3) * 32 + (lane >> 2);      // + mt*16 (+8 for c2,c3)
    int gc = col0 + (wid >> 2) * 64 + (lane & 3) * 2;  // + nt*8

    if (mode == 0) {
        float* base = (is_left ? g_OUT8 : g_XR) + (size_t)z * PLANE;
        bool addb = is_left && (z == 0);
#pragma unroll
        for (int mt = 0; mt < 2; mt++) {
            int r0 = gr + mt * 16;
#pragma unroll
            for (int nt = 0; nt < 8; nt++) {
                int cc = gc + nt * 8;
                float bx = 0.f, by = 0.f;
                if (addb) { bx = bias[cc]; by = bias[cc + 1]; }
                float2 v0 = make_float2(acc[mt][nt][0] + bx, acc[mt][nt][1] + by);
                float2 v1 = make_float2(acc[mt][nt][2] + bx, acc[mt][nt][3] + by);
                *(float2*)(base + (size_t)r0 * 512 + cc)       = v0;
                *(float2*)(base + (size_t)(r0 + 8) * 512 + cc) = v1;
            }
        }
    } else {
#pragma unroll
        for (int mt = 0; mt < 2; mt++) {
#pragma unroll
            for (int half = 0; half < 2; half++) {
                int r = gr + mt * 16 + half * 8;
                int bb, jj;
                if (s == 1) { bb = r; jj = 0; } else { bb = r / 3; jj = r - bb * 3; }
                float* base = g_OUT8 + (size_t)(pb + jj) * PLANE + (size_t)bb * 512;
#pragma unroll
                for (int nt = 0; nt < 8; nt++) {
                    int cc = gc + nt * 8;
                    float2 v = *(float2*)(base + cc);
                    v.x += acc[mt][nt][half * 2];
                    v.y += acc[mt][nt][half * 2 + 1];
                    *(float2*)(base + cc) = v;
                }
            }
        }
    }
}

// ---------------------------------------------------------------------------
// Elementwise kernels
// ---------------------------------------------------------------------------
__device__ __forceinline__ void bsplit(float v, __nv_bfloat16* h, __nv_bfloat16* l) {
    __nv_bfloat16 hh = __float2bfloat16(v);
    *h = hh;
    *l = __float2bfloat16(v - __bfloat162float(hh));
}

__global__ void prep_x_kernel(const float* __restrict__ x) {
    int idx = blockIdx.x * 256 + threadIdx.x;
    const float4* x4 = (const float4*)x;
    float4 a = x4[idx * 2];
    float4 b = x4[idx * 2 + 1];
    float v[8] = {a.x, a.y, a.z, a.w, b.x, b.y, b.z, b.w};
#pragma unroll
    for (int i = 0; i < 8; i++) {
        __nv_bfloat16 h, l;
        bsplit(v[i], &h, &l);
        g_XTh[(size_t)i * PLANE + idx] = h;
        g_XTl[(size_t)i * PLANE + idx] = l;
    }
}

__global__ void prep_w_kernel(const float* __restrict__ weight,
                              const float* __restrict__ w_right,
                              const float* __restrict__ w_left) {
    int idx = blockIdx.x * 256 + threadIdx.x;
    if (idx < WBTOT) {
        int kb = idx >> 18, rem = idx & (WSLICE - 1);
        int m = rem >> 9, n = rem & 511;
        float v = weight[(size_t)(m * 512 + n) * 20 + c_porder[kb]];
        size_t d = (size_t)c_kb_base[kb] + (size_t)m * c_kb_K[kb] + n;
        bsplit(v, &g_WBh[d], &g_WBl[d]);
    } else if (idx < WBTOT + 4 * WSLICE) {
        int t = idx - WBTOT;
        int g = t >> 18, rem = t & (WSLICE - 1);
        int m = rem >> 9, n = rem & 511;
        float v = w_right[(size_t)(m * 512 + n) * 4 + g];
        size_t d = (size_t)g * WSLICE + m * 512 + n;
        bsplit(v, &g_WRh[d], &g_WRl[d]);
    } else {
        int t = idx - WBTOT - 4 * WSLICE;
        int g = t >> 18, rem = t & (WSLICE - 1);
        int m = rem >> 9, n = rem & 511;
        float v = w_left[(size_t)(m * 512 + n) * 4 + g];
        size_t d = (size_t)g * WSLICE + m * 512 + n;
        bsplit(v, &g_WLh[d], &g_WLl[d]);
    }
}

#define QW(off, val) do { float _v = (val); bsplit(_v, &g_Qh[off], &g_Ql[off]); } while (0)

__global__ void qfill_kernel(const float* __restrict__ x,
                             const float* __restrict__ norm_a) {
    int idx = blockIdx.x * 256 + threadIdx.x;   // b*512 + n
    int b = idx >> 9, n = idx & 511;

    const float4* x4 = (const float4*)x;
    float4 xa = x4[idx * 2];
    float4 xb = x4[idx * 2 + 1];
    float x0 = xa.x, x1 = xa.y, x2 = xa.z, x3 = xa.w;
    float x4v = xb.x, x5 = xb.y, x6 = xb.z, x7 = xb.w;

    float r0 = g_XR[0 * PLANE + idx], r1 = g_XR[1 * PLANE + idx];
    float r2 = g_XR[2 * PLANE + idx], r3 = g_XR[3 * PLANE + idx];
    float r4 = g_XR[4 * PLANE + idx], r5 = g_XR[5 * PLANE + idx];
    float r6 = g_XR[6 * PLANE + idx], r7 = g_XR[7 * PLANE + idx];

    float nn[4];
    nn[0] = sqrtf(r0 * r0);
    nn[1] = sqrtf(r1 * r1 + r2 * r2 + r3 * r3);
    nn[2] = sqrtf(r4 * r4 + r5 * r5 + r6 * r6);
    nn[3] = sqrtf(r7 * r7);
    float f[4];
#pragma unroll
    for (int gg = 0; gg < 4; gg++) {
        float a = norm_a[n * 4 + gg];
        float sg = 1.0f / (1.0f + expf(-a));
        f[gg] = sg * (nn[gg] - 1.0f) + 1.0f + 1e-6f;
    }
    r0 /= f[0];
    r1 /= f[1]; r2 /= f[1]; r3 /= f[1];
    r4 /= f[2]; r5 /= f[2]; r6 /= f[2];
    r7 /= f[3];

    {
        size_t q = QOFF0 + (size_t)b * 2048 + n;
        QW(q,        x0 * r0);
        QW(q + 512,  x1 * r1 + x2 * r2 + x3 * r3);
        QW(q + 1024, -(x4v * r4 + x5 * r5 + x6 * r6));
        QW(q + 1536, -(x7 * r7));
    }
    {
        size_t q = QOFF1 + (size_t)(b * 3) * 3072 + n;
        QW(q + 0,    x0 * r1);
        QW(q + 512,  x1 * r0);
        QW(q + 1024, -x2 * r4 - x3 * r5);
        QW(q + 1536, x4v * r2 + x5 * r3);
        QW(q + 2048, -x6 * r7);
        QW(q + 2560, -x7 * r6);
        QW(q + 3072 + 0,    x0 * r2);
        QW(q + 3072 + 512,  x2 * r0);
        QW(q + 3072 + 1024, x1 * r4 - x3 * r6);
        QW(q + 3072 + 1536, -x4v * r1 + x6 * r3);
        QW(q + 3072 + 2048, x5 * r7);
        QW(q + 3072 + 2560, x7 * r5);
        QW(q + 6144 + 0,    x0 * r3);
        QW(q + 6144 + 512,  x3 * r0);
        QW(q + 6144 + 1024, x1 * r5 + x2 * r6);
        QW(q + 6144 + 1536, -x5 * r1 - x6 * r2);
        QW(q + 6144 + 2048, -x4v * r7);
        QW(q + 6144 + 2560, -x7 * r4);
    }
    {
        size_t q = QOFF2 + (size_t)(b * 3) * 3072 + n;
        QW(q + 0,    x0 * r4);
        QW(q + 512,  x1 * r2 - x2 * r1);
        QW(q + 1024, x3 * r7);
        QW(q + 1536, x4v * r0);
        QW(q + 2048, -x5 * r6 + x6 * r5);
        QW(q + 2560, x7 * r3);
        QW(q + 3072 + 0,    x0 * r5);
        QW(q + 3072 + 512,  x1 * r3 - x3 * r1);
        QW(q + 3072 + 1024, -x2 * r7);
        QW(q + 3072 + 1536, x5 * r0);
        QW(q + 3072 + 2048, x4v * r6 - x6 * r4);
        QW(q + 3072 + 2560, -x7 * r2);
        QW(q + 6144 + 0,    x0 * r6);
        QW(q + 6144 + 512,  x2 * r3 - x3 * r2);
        QW(q + 6144 + 1024, x1 * r7);
        QW(q + 6144 + 1536, x6 * r0);
        QW(q + 6144 + 2048, -x4v * r5 + x5 * r4);
        QW(q + 6144 + 2560, x7 * r1);
    }
    {
        size_t q = QOFF3 + (size_t)b * 2048 + n;
        QW(q,        x0 * r7);
        QW(q + 512,  x1 * r6 - x2 * r5 + x3 * r4);
        QW(q + 1024, x4v * r3 - x5 * r2 + x6 * r1);
        QW(q + 1536, x7 * r0);
    }
}

__global__ void merge_out_kernel(float* __restrict__ out) {
    int idx = blockIdx.x * 256 + threadIdx.x;
    const float sc = 0.70710678118654752440f;
    float4 lo, hi;
    lo.x = g_OUT8[0 * PLANE + idx] * sc;
    lo.y = g_OUT8[1 * PLANE + idx] * sc;
    lo.z = g_OUT8[2 * PLANE + idx] * sc;
    lo.w = g_OUT8[3 * PLANE + idx] * sc;
    hi.x = g_OUT8[4 * PLANE + idx] * sc;
    hi.y = g_OUT8[5 * PLANE + idx] * sc;
    hi.z = g_OUT8[6 * PLANE + idx] * sc;
    hi.w = g_OUT8[7 * PLANE + idx] * sc;
    float4* o4 = (float4*)out;
    o4[idx * 2]     = lo;
    o4[idx * 2 + 1] = hi;
}

// ---------------------------------------------------------------------------
extern "C" void kernel_launch(void* const* d_in, const int* in_sizes, int n_in,
                              void* d_out, int out_size) {
    const float* x       = (const float*)d_in[0];
    const float* weight  = (const float*)d_in[1];
    const float* w_right = (const float*)d_in[2];
    const float* w_left  = (const float*)d_in[3];
    const float* b_left  = (const float*)d_in[4];
    const float* norm_a  = (const float*)d_in[5];
    float* out = (float*)d_out;

    cudaFuncSetAttribute(gemm_mma, cudaFuncAttributeMaxDynamicSharedMemorySize,
                         SMEM_BYTES);

    prep_x_kernel<<<PLANE / 256, 256>>>(x);
    prep_w_kernel<<<(WBTOT + 8 * WSLICE) / 256, 256>>>(weight, w_right, w_left);

    gemm_mma<<<dim3(4, 16, 16), 256, SMEM_BYTES>>>(0, b_left);   // XR + LEFT
    qfill_kernel<<<PLANE / 256, 256>>>(x, norm_a);               // gate + Q
    gemm_mma<<<dim3(4, 128, 1), 256, SMEM_BYTES>>>(2, b_left);   // bilinear +=
    merge_out_kernel<<<PLANE / 256, 256>>>(out);
}

// round 6
// speedup vs baseline: 2.6952x; 1.2180x over previous
#include <cuda_runtime.h>
#include <cuda_bf16.h>
#include <cstdint>

// ============================================================================
// Cl(3,0) steerable geometric product layer — baseline-PTX tensor cores.
// mma.sync.m16n8k16 bf16, split hi/lo 3-product fused in one tile residency.
// CTA tile 256x128, warp tile 64x64, 8 warps, 2-stage cp.async (96KB/stage).
// ============================================================================

#define BDIM   2048
#define NIN    512
#define PLANE  (BDIM * NIN)          // 1048576
#define WSLICE (512 * 512)           // 262144

#define QOFF0 0
#define QOFF1 4194304
#define QOFF2 23068672
#define QOFF3 41943040
#define QTOT  46137344

#define WBOFF0 0
#define WBOFF1 1048576
#define WBOFF2 2621440
#define WBOFF3 4194304
#define WBTOT  5242880

__constant__ int c_porder[20] = {0,4,10,16, 1,5,6,11,12,17, 2,7,8,13,14,18, 3,9,15,19};
__constant__ int c_grade[8]   = {0,1,1,1,2,2,2,3};
__constant__ int c_kb_base[20] = {
    WBOFF0+0, WBOFF0+512, WBOFF0+1024, WBOFF0+1536,
    WBOFF1+0, WBOFF1+512, WBOFF1+1024, WBOFF1+1536, WBOFF1+2048, WBOFF1+2560,
    WBOFF2+0, WBOFF2+512, WBOFF2+1024, WBOFF2+1536, WBOFF2+2048, WBOFF2+2560,
    WBOFF3+0, WBOFF3+512, WBOFF3+1024, WBOFF3+1536};
__constant__ int c_kb_K[20] = {2048,2048,2048,2048, 3072,3072,3072,3072,3072,3072,
                               3072,3072,3072,3072,3072,3072, 2048,2048,2048,2048};

__device__ __align__(256) __nv_bfloat16 g_XTh[8 * PLANE];
__device__ __align__(256) __nv_bfloat16 g_XTl[8 * PLANE];
__device__ __align__(256) __nv_bfloat16 g_WRh[4 * WSLICE];
__device__ __align__(256) __nv_bfloat16 g_WRl[4 * WSLICE];
__device__ __align__(256) __nv_bfloat16 g_WLh[4 * WSLICE];
__device__ __align__(256) __nv_bfloat16 g_WLl[4 * WSLICE];
__device__ __align__(256) __nv_bfloat16 g_WBh[WBTOT];
__device__ __align__(256) __nv_bfloat16 g_WBl[WBTOT];
__device__ __align__(256) __nv_bfloat16 g_Qh[QTOT];
__device__ __align__(256) __nv_bfloat16 g_Ql[QTOT];
__device__ float g_XR  [8 * PLANE];
__device__ float g_OUT8[8 * PLANE];

// ---------------------------------------------------------------------------
__device__ __forceinline__ uint32_t s2u(const void* p) {
    return (uint32_t)__cvta_generic_to_shared(p);
}
__device__ __forceinline__ void cp16(uint32_t dst, const void* src) {
    asm volatile("cp.async.cg.shared.global [%0], [%1], 16;\n" :: "r"(dst), "l"(src));
}
#define CP_COMMIT() asm volatile("cp.async.commit_group;\n" ::: "memory")
#define CP_WAIT1()  asm volatile("cp.async.wait_group 1;\n" ::: "memory")
#define CP_WAIT0()  asm volatile("cp.async.wait_group 0;\n" ::: "memory")

__device__ __forceinline__ void ldsm4(uint32_t* r, uint32_t addr) {
    asm volatile("ldmatrix.sync.aligned.m8n8.x4.shared.b16 {%0,%1,%2,%3}, [%4];"
                 : "=r"(r[0]), "=r"(r[1]), "=r"(r[2]), "=r"(r[3]) : "r"(addr));
}
__device__ __forceinline__ void mma_bf16(float* c, const uint32_t* a,
                                         uint32_t b0, uint32_t b1) {
    asm volatile(
        "mma.sync.aligned.m16n8k16.row.col.f32.bf16.bf16.f32 "
        "{%0,%1,%2,%3}, {%4,%5,%6,%7}, {%8,%9}, {%0,%1,%2,%3};"
        : "+f"(c[0]), "+f"(c[1]), "+f"(c[2]), "+f"(c[3])
        : "r"(a[0]), "r"(a[1]), "r"(a[2]), "r"(a[3]), "r"(b0), "r"(b1));
}

#define SWZ(o) ((o) ^ (((o) >> 3) & 0x70))

// Stage layout (96KB): Ah[256x64]@0 (32KB), Al@32768, Bh[128x64]@65536 (16KB),
// Bl@81920. Two stages.
#define STAGE_BYTES 98304u
#define SMEM_BYTES  196608

__device__ __forceinline__ void load_chunk(
    uint32_t sb, int buf,
    const __nv_bfloat16* __restrict__ Ah, const __nv_bfloat16* __restrict__ Al,
    const __nv_bfloat16* __restrict__ Bh, const __nv_bfloat16* __restrict__ Bl,
    int row0, int col0, int Ka, int kt, int tid)
{
    uint32_t st = sb + buf * STAGE_BYTES;
#pragma unroll
    for (int i = 0; i < 8; i++) {             // A: 256 rows x 128B, hi+lo
        int idx = i * 256 + tid;
        int r = idx >> 3, c16 = idx & 7;
        uint32_t so = SWZ((uint32_t)((r << 7) + (c16 << 4)));
        size_t go = (size_t)(row0 + r) * Ka + kt + (c16 << 3);
        cp16(st + so,          Ah + go);
        cp16(st + 32768u + so, Al + go);
    }
#pragma unroll
    for (int i = 0; i < 4; i++) {             // B: 128 rows x 128B, hi+lo
        int idx = i * 256 + tid;
        int r = idx >> 3, c16 = idx & 7;
        uint32_t so = SWZ((uint32_t)((r << 7) + (c16 << 4)));
        size_t go = (size_t)(col0 + r) * Ka + kt + (c16 << 3);
        cp16(st + 65536u + so, Bh + go);
        cp16(st + 81920u + so, Bl + go);
    }
}

// ---------------------------------------------------------------------------
// mode 0: grid (4,8,16)  z<8: XR = XT@WR ; z>=8: OUT8 = XT@WL (+bias z==0)
// mode 2: grid (4,64,1)  OUT8 += Q@WB (grade-grouped rows)
// ---------------------------------------------------------------------------
__global__ void __launch_bounds__(256, 1)
gemm_mma(int mode, const float* __restrict__ bias) {
    extern __shared__ __align__(1024) char smem[];
    uint32_t sb = s2u(smem);
    int tid = threadIdx.x, lane = tid & 31, wid = tid >> 5;
    int wm = wid & 3, wn = wid >> 2;           // 4M x 2N warp grid

    const __nv_bfloat16 *Ah, *Al, *Bh, *Bl;
    int Ka, row0, col0;
    int z = 0, is_left = 0, pb = 0, s = 1;

    if (mode == 0) {
        int zz = blockIdx.z; z = zz & 7; is_left = zz >> 3;
        int g = c_grade[z];
        row0 = blockIdx.y * 256; col0 = blockIdx.x * 128;
        Ka = 512;
        Ah = g_XTh + (size_t)z * PLANE; Al = g_XTl + (size_t)z * PLANE;
        if (is_left) { Bh = g_WLh + (size_t)g * WSLICE; Bl = g_WLl + (size_t)g * WSLICE; }
        else         { Bh = g_WRh + (size_t)g * WSLICE; Bl = g_WRl + (size_t)g * WSLICE; }
    } else {
        int yb = blockIdx.y, g, rb;
        if      (yb < 8)   { g = 0; rb = yb; }
        else if (yb < 32)  { g = 1; rb = yb - 8; }
        else if (yb < 56)  { g = 2; rb = yb - 32; }
        else               { g = 3; rb = yb - 56; }
        size_t qo; int wo;
        if      (g == 0) { Ka = 2048; s = 1; pb = 0; qo = QOFF0; wo = WBOFF0; }
        else if (g == 1) { Ka = 3072; s = 3; pb = 1; qo = QOFF1; wo = WBOFF1; }
        else if (g == 2) { Ka = 3072; s = 3; pb = 4; qo = QOFF2; wo = WBOFF2; }
        else             { Ka = 2048; s = 1; pb = 7; qo = QOFF3; wo = WBOFF3; }
        row0 = rb * 256; col0 = blockIdx.x * 128;
        Ah = g_Qh + qo; Al = g_Ql + qo;
        Bh = g_WBh + wo; Bl = g_WBl + wo;
    }
    int nch = Ka >> 6;

    // lane-constant ldmatrix address pieces
    int a_rowb = wm * 64 + (lane & 15);                            // + mt*16
    int b_rowb = wn * 64 + (lane & 7) + ((lane >> 4) << 3);        // + bt*16
    uint32_t a_colp = (uint32_t)((lane >> 4) << 4);
    uint32_t b_colp = (uint32_t)(((lane >> 3) & 1) << 4);
    uint32_t xmask  = (uint32_t)((lane & 7) << 4);

    float acc[4][8][4];
#pragma unroll
    for (int mt = 0; mt < 4; mt++)
#pragma unroll
        for (int nt = 0; nt < 8; nt++)
#pragma unroll
            for (int q = 0; q < 4; q++) acc[mt][nt][q] = 0.0f;

    load_chunk(sb, 0, Ah, Al, Bh, Bl, row0, col0, Ka, 0, tid);
    CP_COMMIT();

    for (int c = 0; c < nch; c++) {
        int buf = c & 1;
        if (c + 1 < nch) {
            load_chunk(sb, buf ^ 1, Ah, Al, Bh, Bl, row0, col0, Ka, (c + 1) << 6, tid);
            CP_COMMIT();
            CP_WAIT1();
        } else {
            CP_WAIT0();
        }
        __syncthreads();

        uint32_t st  = sb + buf * STAGE_BYTES;
        uint32_t sAh = st, sAl = st + 32768u, sBh = st + 65536u, sBl = st + 81920u;
#pragma unroll
        for (int ks = 0; ks < 4; ks++) {
            uint32_t acol = ((uint32_t)(ks << 5) | a_colp) ^ xmask;
            uint32_t bcol = ((uint32_t)(ks << 5) | b_colp) ^ xmask;
            uint32_t af[4][4], bhf[4][4], blf[4][4];
#pragma unroll
            for (int mt = 0; mt < 4; mt++)
                ldsm4(af[mt], sAh + (uint32_t)((a_rowb + mt * 16) << 7) + acol);
#pragma unroll
            for (int bt = 0; bt < 4; bt++)
                ldsm4(bhf[bt], sBh + (uint32_t)((b_rowb + bt * 16) << 7) + bcol);
            // Ah * Bh
#pragma unroll
            for (int mt = 0; mt < 4; mt++)
#pragma unroll
                for (int nt = 0; nt < 8; nt++)
                    mma_bf16(acc[mt][nt], af[mt], bhf[nt >> 1][(nt & 1) * 2],
                             bhf[nt >> 1][(nt & 1) * 2 + 1]);
#pragma unroll
            for (int bt = 0; bt < 4; bt++)
                ldsm4(blf[bt], sBl + (uint32_t)((b_rowb + bt * 16) << 7) + bcol);
            // Ah * Bl
#pragma unroll
            for (int mt = 0; mt < 4; mt++)
#pragma unroll
                for (int nt = 0; nt < 8; nt++)
                    mma_bf16(acc[mt][nt], af[mt], blf[nt >> 1][(nt & 1) * 2],
                             blf[nt >> 1][(nt & 1) * 2 + 1]);
            // Al * Bh (Al overwrites af)
#pragma unroll
            for (int mt = 0; mt < 4; mt++)
                ldsm4(af[mt], sAl + (uint32_t)((a_rowb + mt * 16) << 7) + acol);
#pragma unroll
            for (int mt = 0; mt < 4; mt++)
#pragma unroll
                for (int nt = 0; nt < 8; nt++)
                    mma_bf16(acc[mt][nt], af[mt], bhf[nt >> 1][(nt & 1) * 2],
                             bhf[nt >> 1][(nt & 1) * 2 + 1]);
        }
        __syncthreads();
    }

    // ---------------- epilogue ----------------
    int gr = row0 + wm * 64 + (lane >> 2);           // + mt*16 (+8)
    int gc = col0 + wn * 64 + (lane & 3) * 2;        // + nt*8

    if (mode == 0) {
        float* base = (is_left ? g_OUT8 : g_XR) + (size_t)z * PLANE;
        bool addb = is_left && (z == 0);
#pragma unroll
        for (int mt = 0; mt < 4; mt++) {
            int r0 = gr + mt * 16;
#pragma unroll
            for (int nt = 0; nt < 8; nt++) {
                int cc = gc + nt * 8;
                float bx = 0.f, by = 0.f;
                if (addb) { bx = bias[cc]; by = bias[cc + 1]; }
                float2 v0 = make_float2(acc[mt][nt][0] + bx, acc[mt][nt][1] + by);
                float2 v1 = make_float2(acc[mt][nt][2] + bx, acc[mt][nt][3] + by);
                *(float2*)(base + (size_t)r0 * 512 + cc)       = v0;
                *(float2*)(base + (size_t)(r0 + 8) * 512 + cc) = v1;
            }
        }
    } else {
#pragma unroll
        for (int mt = 0; mt < 4; mt++) {
#pragma unroll
            for (int half = 0; half < 2; half++) {
                int r = gr + mt * 16 + half * 8;
                int bb, jj;
                if (s == 1) { bb = r; jj = 0; } else { bb = r / 3; jj = r - bb * 3; }
                float* base = g_OUT8 + (size_t)(pb + jj) * PLANE + (size_t)bb * 512;
#pragma unroll
                for (int nt = 0; nt < 8; nt++) {
                    int cc = gc + nt * 8;
                    float2 v = *(float2*)(base + cc);
                    v.x += acc[mt][nt][half * 2];
                    v.y += acc[mt][nt][half * 2 + 1];
                    *(float2*)(base + cc) = v;
                }
            }
        }
    }
}

// ---------------------------------------------------------------------------
// Elementwise kernels
// ---------------------------------------------------------------------------
__device__ __forceinline__ void bsplit(float v, __nv_bfloat16* h, __nv_bfloat16* l) {
    __nv_bfloat16 hh = __float2bfloat16(v);
    *h = hh;
    *l = __float2bfloat16(v - __bfloat162float(hh));
}

__global__ void prep_x_kernel(const float* __restrict__ x) {
    int idx = blockIdx.x * 256 + threadIdx.x;
    const float4* x4 = (const float4*)x;
    float4 a = x4[idx * 2];
    float4 b = x4[idx * 2 + 1];
    float v[8] = {a.x, a.y, a.z, a.w, b.x, b.y, b.z, b.w};
#pragma unroll
    for (int i = 0; i < 8; i++) {
        __nv_bfloat16 h, l;
        bsplit(v[i], &h, &l);
        g_XTh[(size_t)i * PLANE + idx] = h;
        g_XTl[(size_t)i * PLANE + idx] = l;
    }
}

__global__ void prep_w_kernel(const float* __restrict__ weight,
                              const float* __restrict__ w_right,
                              const float* __restrict__ w_left) {
    int idx = blockIdx.x * 256 + threadIdx.x;
    if (idx < WBTOT) {
        int kb = idx >> 18, rem = idx & (WSLICE - 1);
        int m = rem >> 9, n = rem & 511;
        float v = weight[(size_t)(m * 512 + n) * 20 + c_porder[kb]];
        size_t d = (size_t)c_kb_base[kb] + (size_t)m * c_kb_K[kb] + n;
        bsplit(v, &g_WBh[d], &g_WBl[d]);
    } else if (idx < WBTOT + 4 * WSLICE) {
        int t = idx - WBTOT;
        int g = t >> 18, rem = t & (WSLICE - 1);
        int m = rem >> 9, n = rem & 511;
        float v = w_right[(size_t)(m * 512 + n) * 4 + g];
        size_t d = (size_t)g * WSLICE + m * 512 + n;
        bsplit(v, &g_WRh[d], &g_WRl[d]);
    } else {
        int t = idx - WBTOT - 4 * WSLICE;
        int g = t >> 18, rem = t & (WSLICE - 1);
        int m = rem >> 9, n = rem & 511;
        float v = w_left[(size_t)(m * 512 + n) * 4 + g];
        size_t d = (size_t)g * WSLICE + m * 512 + n;
        bsplit(v, &g_WLh[d], &g_WLl[d]);
    }
}

#define QW(off, val) do { float _v = (val); bsplit(_v, &g_Qh[off], &g_Ql[off]); } while (0)

__global__ void qfill_kernel(const float* __restrict__ x,
                             const float* __restrict__ norm_a) {
    int idx = blockIdx.x * 256 + threadIdx.x;   // b*512 + n
    int b = idx >> 9, n = idx & 511;

    const float4* x4 = (const float4*)x;
    float4 xa = x4[idx * 2];
    float4 xb = x4[idx * 2 + 1];
    float x0 = xa.x, x1 = xa.y, x2 = xa.z, x3 = xa.w;
    float x4v = xb.x, x5 = xb.y, x6 = xb.z, x7 = xb.w;

    float r0 = g_XR[0 * PLANE + idx], r1 = g_XR[1 * PLANE + idx];
    float r2 = g_XR[2 * PLANE + idx], r3 = g_XR[3 * PLANE + idx];
    float r4 = g_XR[4 * PLANE + idx], r5 = g_XR[5 * PLANE + idx];
    float r6 = g_XR[6 * PLANE + idx], r7 = g_XR[7 * PLANE + idx];

    float nn[4];
    nn[0] = sqrtf(r0 * r0);
    nn[1] = sqrtf(r1 * r1 + r2 * r2 + r3 * r3);
    nn[2] = sqrtf(r4 * r4 + r5 * r5 + r6 * r6);
    nn[3] = sqrtf(r7 * r7);
    float f[4];
#pragma unroll
    for (int gg = 0; gg < 4; gg++) {
        float a = norm_a[n * 4 + gg];
        float sg = 1.0f / (1.0f + expf(-a));
        f[gg] = sg * (nn[gg] - 1.0f) + 1.0f + 1e-6f;
    }
    r0 /= f[0];
    r1 /= f[1]; r2 /= f[1]; r3 /= f[1];
    r4 /= f[2]; r5 /= f[2]; r6 /= f[2];
    r7 /= f[3];

    {
        size_t q = QOFF0 + (size_t)b * 2048 + n;
        QW(q,        x0 * r0);
        QW(q + 512,  x1 * r1 + x2 * r2 + x3 * r3);
        QW(q + 1024, -(x4v * r4 + x5 * r5 + x6 * r6));
        QW(q + 1536, -(x7 * r7));
    }
    {
        size_t q = QOFF1 + (size_t)(b * 3) * 3072 + n;
        QW(q + 0,    x0 * r1);
        QW(q + 512,  x1 * r0);
        QW(q + 1024, -x2 * r4 - x3 * r5);
        QW(q + 1536, x4v * r2 + x5 * r3);
        QW(q + 2048, -x6 * r7);
        QW(q + 2560, -x7 * r6);
        QW(q + 3072 + 0,    x0 * r2);
        QW(q + 3072 + 512,  x2 * r0);
        QW(q + 3072 + 1024, x1 * r4 - x3 * r6);
        QW(q + 3072 + 1536, -x4v * r1 + x6 * r3);
        QW(q + 3072 + 2048, x5 * r7);
        QW(q + 3072 + 2560, x7 * r5);
        QW(q + 6144 + 0,    x0 * r3);
        QW(q + 6144 + 512,  x3 * r0);
        QW(q + 6144 + 1024, x1 * r5 + x2 * r6);
        QW(q + 6144 + 1536, -x5 * r1 - x6 * r2);
        QW(q + 6144 + 2048, -x4v * r7);
        QW(q + 6144 + 2560, -x7 * r4);
    }
    {
        size_t q = QOFF2 + (size_t)(b * 3) * 3072 + n;
        QW(q + 0,    x0 * r4);
        QW(q + 512,  x1 * r2 - x2 * r1);
        QW(q + 1024, x3 * r7);
        QW(q + 1536, x4v * r0);
        QW(q + 2048, -x5 * r6 + x6 * r5);
        QW(q + 2560, x7 * r3);
        QW(q + 3072 + 0,    x0 * r5);
        QW(q + 3072 + 512,  x1 * r3 - x3 * r1);
        QW(q + 3072 + 1024, -x2 * r7);
        QW(q + 3072 + 1536, x5 * r0);
        QW(q + 3072 + 2048, x4v * r6 - x6 * r4);
        QW(q + 3072 + 2560, -x7 * r2);
        QW(q + 6144 + 0,    x0 * r6);
        QW(q + 6144 + 512,  x2 * r3 - x3 * r2);
        QW(q + 6144 + 1024, x1 * r7);
        QW(q + 6144 + 1536, x6 * r0);
        QW(q + 6144 + 2048, -x4v * r5 + x5 * r4);
        QW(q + 6144 + 2560, x7 * r1);
    }
    {
        size_t q = QOFF3 + (size_t)b * 2048 + n;
        QW(q,        x0 * r7);
        QW(q + 512,  x1 * r6 - x2 * r5 + x3 * r4);
        QW(q + 1024, x4v * r3 - x5 * r2 + x6 * r1);
        QW(q + 1536, x7 * r0);
    }
}

__global__ void merge_out_kernel(float* __restrict__ out) {
    int idx = blockIdx.x * 256 + threadIdx.x;
    const float sc = 0.70710678118654752440f;
    float4 lo, hi;
    lo.x = g_OUT8[0 * PLANE + idx] * sc;
    lo.y = g_OUT8[1 * PLANE + idx] * sc;
    lo.z = g_OUT8[2 * PLANE + idx] * sc;
    lo.w = g_OUT8[3 * PLANE + idx] * sc;
    hi.x = g_OUT8[4 * PLANE + idx] * sc;
    hi.y = g_OUT8[5 * PLANE + idx] * sc;
    hi.z = g_OUT8[6 * PLANE + idx] * sc;
    hi.w = g_OUT8[7 * PLANE + idx] * sc;
    float4* o4 = (float4*)out;
    o4[idx * 2]     = lo;
    o4[idx * 2 + 1] = hi;
}

// ---------------------------------------------------------------------------
extern "C" void kernel_launch(void* const* d_in, const int* in_sizes, int n_in,
                              void* d_out, int out_size) {
    const float* x       = (const float*)d_in[0];
    const float* weight  = (const float*)d_in[1];
    const float* w_right = (const float*)d_in[2];
    const float* w_left  = (const float*)d_in[3];
    const float* b_left  = (const float*)d_in[4];
    const float* norm_a  = (const float*)d_in[5];
    float* out = (float*)d_out;

    cudaFuncSetAttribute(gemm_mma, cudaFuncAttributeMaxDynamicSharedMemorySize,
                         SMEM_BYTES);

    prep_x_kernel<<<PLANE / 256, 256>>>(x);
    prep_w_kernel<<<(WBTOT + 8 * WSLICE) / 256, 256>>>(weight, w_right, w_left);

    gemm_mma<<<dim3(4, 8, 16), 256, SMEM_BYTES>>>(0, b_left);   // XR + LEFT
    qfill_kernel<<<PLANE / 256, 256>>>(x, norm_a);              // gate + Q
    gemm_mma<<<dim3(4, 64, 1), 256, SMEM_BYTES>>>(2, b_left);   // bilinear +=
    merge_out_kernel<<<PLANE / 256, 256>>>(out);
}

// round 9
// speedup vs baseline: 3.4974x; 1.2976x over previous
#include <cuda_runtime.h>
#include <cuda_fp16.h>
#include <cstdint>

// ============================================================================
// Cl(3,0) steerable geometric product layer — baseline-PTX tensor cores.
// fp16 mma.sync.m16n8k16, A-side split hi/lo (2 products); the XR GEMM adds a
// third product (B residual) to stop error propagation through the gating.
// CTA tile 256x128, warp tile 64x64, 8 warps, 2-stage cp.async.
// ============================================================================

#define BDIM   2048
#define NIN    512
#define PLANE  (BDIM * NIN)          // 1048576
#define WSLICE (512 * 512)           // 262144

#define QOFF0 0
#define QOFF1 4194304
#define QOFF2 23068672
#define QOFF3 41943040
#define QTOT  46137344

#define WBOFF0 0
#define WBOFF1 1048576
#define WBOFF2 2621440
#define WBOFF3 4194304
#define WBTOT  5242880

__constant__ int c_porder[20] = {0,4,10,16, 1,5,6,11,12,17, 2,7,8,13,14,18, 3,9,15,19};
__constant__ int c_grade[8]   = {0,1,1,1,2,2,2,3};
__constant__ int c_kb_base[20] = {
    WBOFF0+0, WBOFF0+512, WBOFF0+1024, WBOFF0+1536,
    WBOFF1+0, WBOFF1+512, WBOFF1+1024, WBOFF1+1536, WBOFF1+2048, WBOFF1+2560,
    WBOFF2+0, WBOFF2+512, WBOFF2+1024, WBOFF2+1536, WBOFF2+2048, WBOFF2+2560,
    WBOFF3+0, WBOFF3+512, WBOFF3+1024, WBOFF3+1536};
__constant__ int c_kb_K[20] = {2048,2048,2048,2048, 3072,3072,3072,3072,3072,3072,
                               3072,3072,3072,3072,3072,3072, 2048,2048,2048,2048};

__device__ __align__(256) __half g_XTh[8 * PLANE];
__device__ __align__(256) __half g_XTl[8 * PLANE];
__device__ __align__(256) __half g_WRh[4 * WSLICE];
__device__ __align__(256) __half g_WRl[4 * WSLICE];   // B residual for XR GEMM
__device__ __align__(256) __half g_WL [4 * WSLICE];
__device__ __align__(256) __half g_WB [WBTOT];
__device__ __align__(256) __half g_Qh[QTOT];
__device__ __align__(256) __half g_Ql[QTOT];
__device__ float g_XR  [8 * PLANE];
__device__ float g_OUT8[8 * PLANE];

// ---------------------------------------------------------------------------
__device__ __forceinline__ uint32_t s2u(const void* p) {
    return (uint32_t)__cvta_generic_to_shared(p);
}
__device__ __forceinline__ void cp16(uint32_t dst, const void* src) {
    asm volatile("cp.async.cg.shared.global [%0], [%1], 16;\n" :: "r"(dst), "l"(src));
}
#define CP_COMMIT() asm volatile("cp.async.commit_group;\n" ::: "memory")
#define CP_WAIT1()  asm volatile("cp.async.wait_group 1;\n" ::: "memory")
#define CP_WAIT0()  asm volatile("cp.async.wait_group 0;\n" ::: "memory")

__device__ __forceinline__ void ldsm4(uint32_t* r, uint32_t addr) {
    asm volatile("ldmatrix.sync.aligned.m8n8.x4.shared.b16 {%0,%1,%2,%3}, [%4];"
                 : "=r"(r[0]), "=r"(r[1]), "=r"(r[2]), "=r"(r[3]) : "r"(addr));
}
__device__ __forceinline__ void mma_fp16(float* c, const uint32_t* a,
                                         uint32_t b0, uint32_t b1) {
    asm volatile(
        "mma.sync.aligned.m16n8k16.row.col.f32.f16.f16.f32 "
        "{%0,%1,%2,%3}, {%4,%5,%6,%7}, {%8,%9}, {%0,%1,%2,%3};"
        : "+f"(c[0]), "+f"(c[1]), "+f"(c[2]), "+f"(c[3])
        : "r"(a[0]), "r"(a[1]), "r"(a[2]), "r"(a[3]), "r"(b0), "r"(b1));
}

#define SWZ(o) ((o) ^ (((o) >> 3) & 0x70))

// Stage (96KB): Ah[256x64]@0 (32KB), Al@32768, Bh[128x64]@65536 (16KB), Bl@81920.
#define STAGE_BYTES 98304u
#define SMEM_BYTES  196608

__device__ __forceinline__ void load_chunk(
    uint32_t sb, int buf,
    const __half* __restrict__ Ah, const __half* __restrict__ Al,
    const __half* __restrict__ Bh, const __half* __restrict__ Bl,
    int row0, int col0, int Ka, int kt, int tid, int nprod3)
{
    uint32_t st = sb + buf * STAGE_BYTES;
#pragma unroll
    for (int i = 0; i < 8; i++) {             // A: 256 rows x 128B, hi+lo
        int idx = i * 256 + tid;
        int r = idx >> 3, c16 = idx & 7;
        uint32_t so = SWZ((uint32_t)((r << 7) + (c16 << 4)));
        size_t go = (size_t)(row0 + r) * Ka + kt + (c16 << 3);
        cp16(st + so,          Ah + go);
        cp16(st + 32768u + so, Al + go);
    }
#pragma unroll
    for (int i = 0; i < 4; i++) {             // B: 128 rows x 128B
        int idx = i * 256 + tid;
        int r = idx >> 3, c16 = idx & 7;
        uint32_t so = SWZ((uint32_t)((r << 7) + (c16 << 4)));
        size_t go = (size_t)(col0 + r) * Ka + kt + (c16 << 3);
        cp16(st + 65536u + so, Bh + go);
        if (nprod3) cp16(st + 81920u + so, Bl + go);
    }
}

// ---------------------------------------------------------------------------
// mode 0: grid (4,8,16)  z<8: XR = XT@WR (3 products); z>=8: OUT8 = XT@WL (+bias)
// mode 2: grid (4,64,1)  OUT8 += Q@WB (grade-grouped rows, 2 products)
// ---------------------------------------------------------------------------
__global__ void __launch_bounds__(256, 1)
gemm_mma(int mode, const float* __restrict__ bias) {
    extern __shared__ __align__(1024) char smem[];
    uint32_t sb = s2u(smem);
    int tid = threadIdx.x, lane = tid & 31, wid = tid >> 5;
    int wm = wid & 3, wn = wid >> 2;           // 4M x 2N warp grid

    const __half *Ah, *Al, *Bh, *Bl = nullptr;
    int Ka, row0, col0, nprod3 = 0;
    int z = 0, is_left = 0, pb = 0, s = 1;

    if (mode == 0) {
        int zz = blockIdx.z; z = zz & 7; is_left = zz >> 3;
        int g = c_grade[z];
        row0 = blockIdx.y * 256; col0 = blockIdx.x * 128;
        Ka = 512;
        Ah = g_XTh + (size_t)z * PLANE; Al = g_XTl + (size_t)z * PLANE;
        if (is_left) { Bh = g_WL + (size_t)g * WSLICE; }
        else         { Bh = g_WRh + (size_t)g * WSLICE;
                       Bl = g_WRl + (size_t)g * WSLICE; nprod3 = 1; }
    } else {
        int yb = blockIdx.y, g, rb;
        if      (yb < 8)   { g = 0; rb = yb; }
        else if (yb < 32)  { g = 1; rb = yb - 8; }
        else if (yb < 56)  { g = 2; rb = yb - 32; }
        else               { g = 3; rb = yb - 56; }
        size_t qo; int wo;
        if      (g == 0) { Ka = 2048; s = 1; pb = 0; qo = QOFF0; wo = WBOFF0; }
        else if (g == 1) { Ka = 3072; s = 3; pb = 1; qo = QOFF1; wo = WBOFF1; }
        else if (g == 2) { Ka = 3072; s = 3; pb = 4; qo = QOFF2; wo = WBOFF2; }
        else             { Ka = 2048; s = 1; pb = 7; qo = QOFF3; wo = WBOFF3; }
        row0 = rb * 256; col0 = blockIdx.x * 128;
        Ah = g_Qh + qo; Al = g_Ql + qo;
        Bh = g_WB + wo;
    }
    int nch = Ka >> 6;

    // lane-constant ldmatrix address pieces
    int a_rowb = wm * 64 + (lane & 15);                            // + mt*16
    int b_rowb = wn * 64 + (lane & 7) + ((lane >> 4) << 3);        // + bt*16
    uint32_t a_colp = (uint32_t)((lane >> 4) << 4);
    uint32_t b_colp = (uint32_t)(((lane >> 3) & 1) << 4);
    uint32_t xmask  = (uint32_t)((lane & 7) << 4);

    float acc[4][8][4];
#pragma unroll
    for (int mt = 0; mt < 4; mt++)
#pragma unroll
        for (int nt = 0; nt < 8; nt++)
#pragma unroll
            for (int q = 0; q < 4; q++) acc[mt][nt][q] = 0.0f;

    load_chunk(sb, 0, Ah, Al, Bh, Bl, row0, col0, Ka, 0, tid, nprod3);
    CP_COMMIT();

    for (int c = 0; c < nch; c++) {
        int buf = c & 1;
        if (c + 1 < nch) {
            load_chunk(sb, buf ^ 1, Ah, Al, Bh, Bl, row0, col0, Ka,
                       (c + 1) << 6, tid, nprod3);
            CP_COMMIT();
            CP_WAIT1();
        } else {
            CP_WAIT0();
        }
        __syncthreads();

        uint32_t st  = sb + buf * STAGE_BYTES;
        uint32_t sAh = st, sAl = st + 32768u, sBh = st + 65536u, sBl = st + 81920u;
#pragma unroll
        for (int ks = 0; ks < 4; ks++) {
            uint32_t acol = ((uint32_t)(ks << 5) | a_colp) ^ xmask;
            uint32_t bcol = ((uint32_t)(ks << 5) | b_colp) ^ xmask;
            uint32_t af[4][4], bhf[4][4];
#pragma unroll
            for (int mt = 0; mt < 4; mt++)
                ldsm4(af[mt], sAh + (uint32_t)((a_rowb + mt * 16) << 7) + acol);
#pragma unroll
            for (int bt = 0; bt < 4; bt++)
                ldsm4(bhf[bt], sBh + (uint32_t)((b_rowb + bt * 16) << 7) + bcol);
            // Ah * Bh
#pragma unroll
            for (int mt = 0; mt < 4; mt++)
#pragma unroll
                for (int nt = 0; nt < 8; nt++)
                    mma_fp16(acc[mt][nt], af[mt], bhf[nt >> 1][(nt & 1) * 2],
                             bhf[nt >> 1][(nt & 1) * 2 + 1]);
            // Ah * Bl (XR GEMM only)
            if (nprod3) {
                uint32_t blf[4][4];
#pragma unroll
                for (int bt = 0; bt < 4; bt++)
                    ldsm4(blf[bt], sBl + (uint32_t)((b_rowb + bt * 16) << 7) + bcol);
#pragma unroll
                for (int mt = 0; mt < 4; mt++)
#pragma unroll
                    for (int nt = 0; nt < 8; nt++)
                        mma_fp16(acc[mt][nt], af[mt], blf[nt >> 1][(nt & 1) * 2],
                                 blf[nt >> 1][(nt & 1) * 2 + 1]);
            }
            // Al * Bh
#pragma unroll
            for (int mt = 0; mt < 4; mt++)
                ldsm4(af[mt], sAl + (uint32_t)((a_rowb + mt * 16) << 7) + acol);
#pragma unroll
            for (int mt = 0; mt < 4; mt++)
#pragma unroll
                for (int nt = 0; nt < 8; nt++)
                    mma_fp16(acc[mt][nt], af[mt], bhf[nt >> 1][(nt & 1) * 2],
                             bhf[nt >> 1][(nt & 1) * 2 + 1]);
        }
        __syncthreads();
    }

    // ---------------- epilogue ----------------
    int gr = row0 + wm * 64 + (lane >> 2);           // + mt*16 (+8)
    int gc = col0 + wn * 64 + (lane & 3) * 2;        // + nt*8

    if (mode == 0) {
        float* base = (is_left ? g_OUT8 : g_XR) + (size_t)z * PLANE;
        bool addb = is_left && (z == 0);
#pragma unroll
        for (int mt = 0; mt < 4; mt++) {
            int r0 = gr + mt * 16;
#pragma unroll
            for (int nt = 0; nt < 8; nt++) {
                int cc = gc + nt * 8;
                float bx = 0.f, by = 0.f;
                if (addb) { bx = bias[cc]; by = bias[cc + 1]; }
                float2 v0 = make_float2(acc[mt][nt][0] + bx, acc[mt][nt][1] + by);
                float2 v1 = make_float2(acc[mt][nt][2] + bx, acc[mt][nt][3] + by);
                *(float2*)(base + (size_t)r0 * 512 + cc)       = v0;
                *(float2*)(base + (size_t)(r0 + 8) * 512 + cc) = v1;
            }
        }
    } else {
#pragma unroll
        for (int mt = 0; mt < 4; mt++) {
#pragma unroll
            for (int half = 0; half < 2; half++) {
                int r = gr + mt * 16 + half * 8;
                int bb, jj;
                if (s == 1) { bb = r; jj = 0; } else { bb = r / 3; jj = r - bb * 3; }
                float* base = g_OUT8 + (size_t)(pb + jj) * PLANE + (size_t)bb * 512;
#pragma unroll
                for (int nt = 0; nt < 8; nt++) {
                    int cc = gc + nt * 8;
                    float2 v = *(float2*)(base + cc);
                    v.x += acc[mt][nt][half * 2];
                    v.y += acc[mt][nt][half * 2 + 1];
                    *(float2*)(base + cc) = v;
                }
            }
        }
    }
}

// ---------------------------------------------------------------------------
// Elementwise kernels
// ---------------------------------------------------------------------------
__device__ __forceinline__ void hsplit(float v, __half* h, __half* l) {
    __half hh = __float2half_rn(v);
    *h = hh;
    *l = __float2half_rn(v - __half2float(hh));
}

__global__ void prep_x_kernel(const float* __restrict__ x) {
    int idx = blockIdx.x * 256 + threadIdx.x;
    const float4* x4 = (const float4*)x;
    float4 a = x4[idx * 2];
    float4 b = x4[idx * 2 + 1];
    float v[8] = {a.x, a.y, a.z, a.w, b.x, b.y, b.z, b.w};
#pragma unroll
    for (int i = 0; i < 8; i++) {
        __half h, l;
        hsplit(v[i], &h, &l);
        g_XTh[(size_t)i * PLANE + idx] = h;
        g_XTl[(size_t)i * PLANE + idx] = l;
    }
}

__global__ void prep_w_kernel(const float* __restrict__ weight,
                              const float* __restrict__ w_right,
                              const float* __restrict__ w_left) {
    int idx = blockIdx.x * 256 + threadIdx.x;
    if (idx < WBTOT) {
        int kb = idx >> 18, rem = idx & (WSLICE - 1);
        int m = rem >> 9, n = rem & 511;
        float v = weight[(size_t)(m * 512 + n) * 20 + c_porder[kb]];
        size_t d = (size_t)c_kb_base[kb] + (size_t)m * c_kb_K[kb] + n;
        g_WB[d] = __float2half_rn(v);
    } else if (idx < WBTOT + 4 * WSLICE) {
        int t = idx - WBTOT;
        int g = t >> 18, rem = t & (WSLICE - 1);
        int m = rem >> 9, n = rem & 511;
        float v = w_right[(size_t)(m * 512 + n) * 4 + g];
        size_t d = (size_t)g * WSLICE + m * 512 + n;
        hsplit(v, &g_WRh[d], &g_WRl[d]);
    } else {
        int t = idx - WBTOT - 4 * WSLICE;
        int g = t >> 18, rem = t & (WSLICE - 1);
        int m = rem >> 9, n = rem & 511;
        float v = w_left[(size_t)(m * 512 + n) * 4 + g];
        size_t d = (size_t)g * WSLICE + m * 512 + n;
        g_WL[d] = __float2half_rn(v);
    }
}

#define QW(off, val) do { float _v = (val); hsplit(_v, &g_Qh[off], &g_Ql[off]); } while (0)

__global__ void qfill_kernel(const float* __restrict__ x,
                             const float* __restrict__ norm_a) {
    int idx = blockIdx.x * 256 + threadIdx.x;   // b*512 + n
    int b = idx >> 9, n = idx & 511;

    const float4* x4 = (const float4*)x;
    float4 xa = x4[idx * 2];
    float4 xb = x4[idx * 2 + 1];
    float x0 = xa.x, x1 = xa.y, x2 = xa.z, x3 = xa.w;
    float x4v = xb.x, x5 = xb.y, x6 = xb.z, x7 = xb.w;

    float r0 = g_XR[0 * PLANE + idx], r1 = g_XR[1 * PLANE + idx];
    float r2 = g_XR[2 * PLANE + idx], r3 = g_XR[3 * PLANE + idx];
    float r4 = g_XR[4 * PLANE + idx], r5 = g_XR[5 * PLANE + idx];
    float r6 = g_XR[6 * PLANE + idx], r7 = g_XR[7 * PLANE + idx];

    float nn[4];
    nn[0] = sqrtf(r0 * r0);
    nn[1] = sqrtf(r1 * r1 + r2 * r2 + r3 * r3);
    nn[2] = sqrtf(r4 * r4 + r5 * r5 + r6 * r6);
    nn[3] = sqrtf(r7 * r7);
    float f[4];
#pragma unroll
    for (int gg = 0; gg < 4; gg++) {
        float a = norm_a[n * 4 + gg];
        float sg = 1.0f / (1.0f + expf(-a));
        f[gg] = sg * (nn[gg] - 1.0f) + 1.0f + 1e-6f;
    }
    r0 /= f[0];
    r1 /= f[1]; r2 /= f[1]; r3 /= f[1];
    r4 /= f[2]; r5 /= f[2]; r6 /= f[2];
    r7 /= f[3];

    {
        size_t q = QOFF0 + (size_t)b * 2048 + n;
        QW(q,        x0 * r0);
        QW(q + 512,  x1 * r1 + x2 * r2 + x3 * r3);
        QW(q + 1024, -(x4v * r4 + x5 * r5 + x6 * r6));
        QW(q + 1536, -(x7 * r7));
    }
    {
        size_t q = QOFF1 + (size_t)(b * 3) * 3072 + n;
        QW(q + 0,    x0 * r1);
        QW(q + 512,  x1 * r0);
        QW(q + 1024, -x2 * r4 - x3 * r5);
        QW(q + 1536, x4v * r2 + x5 * r3);
        QW(q + 2048, -x6 * r7);
        QW(q + 2560, -x7 * r6);
        QW(q + 3072 + 0,    x0 * r2);
        QW(q + 3072 + 512,  x2 * r0);
        QW(q + 3072 + 1024, x1 * r4 - x3 * r6);
        QW(q + 3072 + 1536, -x4v * r1 + x6 * r3);
        QW(q + 3072 + 2048, x5 * r7);
        QW(q + 3072 + 2560, x7 * r5);
        QW(q + 6144 + 0,    x0 * r3);
        QW(q + 6144 + 512,  x3 * r0);
        QW(q + 6144 + 1024, x1 * r5 + x2 * r6);
        QW(q + 6144 + 1536, -x5 * r1 - x6 * r2);
        QW(q + 6144 + 2048, -x4v * r7);
        QW(q + 6144 + 2560, -x7 * r4);
    }
    {
        size_t q = QOFF2 + (size_t)(b * 3) * 3072 + n;
        QW(q + 0,    x0 * r4);
        QW(q + 512,  x1 * r2 - x2 * r1);
        QW(q + 1024, x3 * r7);
        QW(q + 1536, x4v * r0);
        QW(q + 2048, -x5 * r6 + x6 * r5);
        QW(q + 2560, x7 * r3);
        QW(q + 3072 + 0,    x0 * r5);
        QW(q + 3072 + 512,  x1 * r3 - x3 * r1);
        QW(q + 3072 + 1024, -x2 * r7);
        QW(q + 3072 + 1536, x5 * r0);
        QW(q + 3072 + 2048, x4v * r6 - x6 * r4);
        QW(q + 3072 + 2560, -x7 * r2);
        QW(q + 6144 + 0,    x0 * r6);
        QW(q + 6144 + 512,  x2 * r3 - x3 * r2);
        QW(q + 6144 + 1024, x1 * r7);
        QW(q + 6144 + 1536, x6 * r0);
        QW(q + 6144 + 2048, -x4v * r5 + x5 * r4);
        QW(q + 6144 + 2560, x7 * r1);
    }
    {
        size_t q = QOFF3 + (size_t)b * 2048 + n;
        QW(q,        x0 * r7);
        QW(q + 512,  x1 * r6 - x2 * r5 + x3 * r4);
        QW(q + 1024, x4v * r3 - x5 * r2 + x6 * r1);
        QW(q + 1536, x7 * r0);
    }
}

__global__ void merge_out_kernel(float* __restrict__ out) {
    int idx = blockIdx.x * 256 + threadIdx.x;
    const float sc = 0.70710678118654752440f;
    float4 lo, hi;
    lo.x = g_OUT8[0 * PLANE + idx] * sc;
    lo.y = g_OUT8[1 * PLANE + idx] * sc;
    lo.z = g_OUT8[2 * PLANE + idx] * sc;
    lo.w = g_OUT8[3 * PLANE + idx] * sc;
    hi.x = g_OUT8[4 * PLANE + idx] * sc;
    hi.y = g_OUT8[5 * PLANE + idx] * sc;
    hi.z = g_OUT8[6 * PLANE + idx] * sc;
    hi.w = g_OUT8[7 * PLANE + idx] * sc;
    float4* o4 = (float4*)out;
    o4[idx * 2]     = lo;
    o4[idx * 2 + 1] = hi;
}

// ---------------------------------------------------------------------------
extern "C" void kernel_launch(void* const* d_in, const int* in_sizes, int n_in,
                              void* d_out, int out_size) {
    const float* x       = (const float*)d_in[0];
    const float* weight  = (const float*)d_in[1];
    const float* w_right = (const float*)d_in[2];
    const float* w_left  = (const float*)d_in[3];
    const float* b_left  = (const float*)d_in[4];
    const float* norm_a  = (const float*)d_in[5];
    float* out = (float*)d_out;

    cudaFuncSetAttribute(gemm_mma, cudaFuncAttributeMaxDynamicSharedMemorySize,
                         SMEM_BYTES);

    prep_x_kernel<<<PLANE / 256, 256>>>(x);
    prep_w_kernel<<<(WBTOT + 8 * WSLICE) / 256, 256>>>(weight, w_right, w_left);

    gemm_mma<<<dim3(4, 8, 16), 256, SMEM_BYTES>>>(0, b_left);   // XR + LEFT
    qfill_kernel<<<PLANE / 256, 256>>>(x, norm_a);              // gate + Q
    gemm_mma<<<dim3(4, 64, 1), 256, SMEM_BYTES>>>(2, b_left);   // bilinear +=
    merge_out_kernel<<<PLANE / 256, 256>>>(out);
}

// round 12
// speedup vs baseline: 5.1081x; 1.4606x over previous
#include <cuda_runtime.h>
#include <cuda_fp16.h>
#include <cstdint>

// ============================================================================
// Cl(3,0) steerable geometric product layer — baseline-PTX tensor cores.
// fp16 mma.sync.m16n8k16.
//   XR GEMM:  split-A (hi/lo) + split-B residual  -> 3 products (high accuracy
//             feeding the gating nonlinearity)
//   Fused bilinear+left GEMM: Q channels single fp16 (1 product) + 8 trailing
//             K-chunks of XT (split hi/lo, 2 products) against WL, bias fused.
// CTA tile 256x128, warp tile 64x64, 8 warps, 2-stage cp.async.
// ============================================================================

#define BDIM   2048
#define NIN    512
#define PLANE  (BDIM * NIN)          // 1048576
#define WSLICE (512 * 512)           // 262144

#define QOFF0 0
#define QOFF1 4194304
#define QOFF2 23068672
#define QOFF3 41943040
#define QTOT  46137344

#define WBOFF0 0
#define WBOFF1 1048576
#define WBOFF2 2621440
#define WBOFF3 4194304
#define WBTOT  5242880

__constant__ int c_porder[20] = {0,4,10,16, 1,5,6,11,12,17, 2,7,8,13,14,18, 3,9,15,19};
__constant__ int c_grade[8]   = {0,1,1,1,2,2,2,3};
__constant__ int c_kb_base[20] = {
    WBOFF0+0, WBOFF0+512, WBOFF0+1024, WBOFF0+1536,
    WBOFF1+0, WBOFF1+512, WBOFF1+1024, WBOFF1+1536, WBOFF1+2048, WBOFF1+2560,
    WBOFF2+0, WBOFF2+512, WBOFF2+1024, WBOFF2+1536, WBOFF2+2048, WBOFF2+2560,
    WBOFF3+0, WBOFF3+512, WBOFF3+1024, WBOFF3+1536};
__constant__ int c_kb_K[20] = {2048,2048,2048,2048, 3072,3072,3072,3072,3072,3072,
                               3072,3072,3072,3072,3072,3072, 2048,2048,2048,2048};

__device__ __align__(256) __half g_XTh[8 * PLANE];
__device__ __align__(256) __half g_XTl[8 * PLANE];
__device__ __align__(256) __half g_WRh[4 * WSLICE];
__device__ __align__(256) __half g_WRl[4 * WSLICE];   // B residual for XR GEMM
__device__ __align__(256) __half g_WL [4 * WSLICE];
__device__ __align__(256) __half g_WB [WBTOT];
__device__ __align__(256) __half g_Q  [QTOT];
__device__ float g_XR  [8 * PLANE];
__device__ float g_OUT8[8 * PLANE];

// ---------------------------------------------------------------------------
__device__ __forceinline__ uint32_t s2u(const void* p) {
    return (uint32_t)__cvta_generic_to_shared(p);
}
__device__ __forceinline__ void cp16(uint32_t dst, const void* src) {
    asm volatile("cp.async.cg.shared.global [%0], [%1], 16;\n" :: "r"(dst), "l"(src));
}
#define CP_COMMIT() asm volatile("cp.async.commit_group;\n" ::: "memory")
#define CP_WAIT1()  asm volatile("cp.async.wait_group 1;\n" ::: "memory")
#define CP_WAIT0()  asm volatile("cp.async.wait_group 0;\n" ::: "memory")

__device__ __forceinline__ void ldsm4(uint32_t* r, uint32_t addr) {
    asm volatile("ldmatrix.sync.aligned.m8n8.x4.shared.b16 {%0,%1,%2,%3}, [%4];"
                 : "=r"(r[0]), "=r"(r[1]), "=r"(r[2]), "=r"(r[3]) : "r"(addr));
}
__device__ __forceinline__ void mma_fp16(float* c, const uint32_t* a,
                                         uint32_t b0, uint32_t b1) {
    asm volatile(
        "mma.sync.aligned.m16n8k16.row.col.f32.f16.f16.f32 "
        "{%0,%1,%2,%3}, {%4,%5,%6,%7}, {%8,%9}, {%0,%1,%2,%3};"
        : "+f"(c[0]), "+f"(c[1]), "+f"(c[2]), "+f"(c[3])
        : "r"(a[0]), "r"(a[1]), "r"(a[2]), "r"(a[3]), "r"(b0), "r"(b1));
}

#define SWZ(o) ((o) ^ (((o) >> 3) & 0x70))

// Stage (96KB): Ah[256x64]@0 (32KB), Al@32768 (32KB), B@65536 (16KB), B2@81920.
#define STAGE_BYTES 98304u
#define SMEM_BYTES  196608

// ---------------------------------------------------------------------------
// XR GEMM: XR[z] = XT[z] @ WR[g(z)], 3 products (Ah*Bh, Ah*Bl, Al*Bh).
// grid (4, 8, 8): x=col/128, y=row/256, z=blade.
// ---------------------------------------------------------------------------
__global__ void __launch_bounds__(256, 1)
gemm_xr() {
    extern __shared__ __align__(1024) char smem[];
    uint32_t sb = s2u(smem);
    int tid = threadIdx.x, lane = tid & 31, wid = tid >> 5;
    int wm = wid & 3, wn = wid >> 2;

    int z = blockIdx.z, g = c_grade[z];
    int row0 = blockIdx.y * 256, col0 = blockIdx.x * 128;
    const __half* Ah = g_XTh + (size_t)z * PLANE;
    const __half* Al = g_XTl + (size_t)z * PLANE;
    const __half* Bh = g_WRh + (size_t)g * WSLICE;
    const __half* Bl = g_WRl + (size_t)g * WSLICE;

    int a_rowb = wm * 64 + (lane & 15);
    int b_rowb = wn * 64 + (lane & 7) + ((lane >> 4) << 3);
    uint32_t a_colp = (uint32_t)((lane >> 4) << 4);
    uint32_t b_colp = (uint32_t)(((lane >> 3) & 1) << 4);
    uint32_t xmask  = (uint32_t)((lane & 7) << 4);

    float acc[4][8][4];
#pragma unroll
    for (int mt = 0; mt < 4; mt++)
#pragma unroll
        for (int nt = 0; nt < 8; nt++)
#pragma unroll
            for (int q = 0; q < 4; q++) acc[mt][nt][q] = 0.0f;

    auto load = [&](int buf, int kt) {
        uint32_t st = sb + buf * STAGE_BYTES;
#pragma unroll
        for (int i = 0; i < 8; i++) {
            int idx = i * 256 + tid;
            int r = idx >> 3, c16 = idx & 7;
            uint32_t so = SWZ((uint32_t)((r << 7) + (c16 << 4)));
            size_t go = (size_t)(row0 + r) * 512 + kt + (c16 << 3);
            cp16(st + so,          Ah + go);
            cp16(st + 32768u + so, Al + go);
        }
#pragma unroll
        for (int i = 0; i < 4; i++) {
            int idx = i * 256 + tid;
            int r = idx >> 3, c16 = idx & 7;
            uint32_t so = SWZ((uint32_t)((r << 7) + (c16 << 4)));
            size_t go = (size_t)(col0 + r) * 512 + kt + (c16 << 3);
            cp16(st + 65536u + so, Bh + go);
            cp16(st + 81920u + so, Bl + go);
        }
    };

    load(0, 0);
    CP_COMMIT();
    const int nch = 8;
    for (int c = 0; c < nch; c++) {
        int buf = c & 1;
        if (c + 1 < nch) { load(buf ^ 1, (c + 1) << 6); CP_COMMIT(); CP_WAIT1(); }
        else             { CP_WAIT0(); }
        __syncthreads();

        uint32_t st  = sb + buf * STAGE_BYTES;
        uint32_t sAh = st, sAl = st + 32768u, sBh = st + 65536u, sBl = st + 81920u;
#pragma unroll
        for (int ks = 0; ks < 4; ks++) {
            uint32_t acol = ((uint32_t)(ks << 5) | a_colp) ^ xmask;
            uint32_t bcol = ((uint32_t)(ks << 5) | b_colp) ^ xmask;
            uint32_t af[4][4], bhf[4][4], blf[4][4];
#pragma unroll
            for (int mt = 0; mt < 4; mt++)
                ldsm4(af[mt], sAh + (uint32_t)((a_rowb + mt * 16) << 7) + acol);
#pragma unroll
            for (int bt = 0; bt < 4; bt++)
                ldsm4(bhf[bt], sBh + (uint32_t)((b_rowb + bt * 16) << 7) + bcol);
#pragma unroll
            for (int mt = 0; mt < 4; mt++)
#pragma unroll
                for (int nt = 0; nt < 8; nt++)
                    mma_fp16(acc[mt][nt], af[mt], bhf[nt >> 1][(nt & 1) * 2],
                             bhf[nt >> 1][(nt & 1) * 2 + 1]);
#pragma unroll
            for (int bt = 0; bt < 4; bt++)
                ldsm4(blf[bt], sBl + (uint32_t)((b_rowb + bt * 16) << 7) + bcol);
#pragma unroll
            for (int mt = 0; mt < 4; mt++)
#pragma unroll
                for (int nt = 0; nt < 8; nt++)
                    mma_fp16(acc[mt][nt], af[mt], blf[nt >> 1][(nt & 1) * 2],
                             blf[nt >> 1][(nt & 1) * 2 + 1]);
#pragma unroll
            for (int mt = 0; mt < 4; mt++)
                ldsm4(af[mt], sAl + (uint32_t)((a_rowb + mt * 16) << 7) + acol);
#pragma unroll
            for (int mt = 0; mt < 4; mt++)
#pragma unroll
                for (int nt = 0; nt < 8; nt++)
                    mma_fp16(acc[mt][nt], af[mt], bhf[nt >> 1][(nt & 1) * 2],
                             bhf[nt >> 1][(nt & 1) * 2 + 1]);
        }
        __syncthreads();
    }

    int gr = row0 + wm * 64 + (lane >> 2);
    int gc = col0 + wn * 64 + (lane & 3) * 2;
    float* base = g_XR + (size_t)z * PLANE;
#pragma unroll
    for (int mt = 0; mt < 4; mt++) {
        int r0 = gr + mt * 16;
#pragma unroll
        for (int nt = 0; nt < 8; nt++) {
            int cc = gc + nt * 8;
            *(float2*)(base + (size_t)r0 * 512 + cc) =
                make_float2(acc[mt][nt][0], acc[mt][nt][1]);
            *(float2*)(base + (size_t)(r0 + 8) * 512 + cc) =
                make_float2(acc[mt][nt][2], acc[mt][nt][3]);
        }
    }
}

// ---------------------------------------------------------------------------
// Fused bilinear + left GEMM.
// grid (4, 64): y -> (grade, row-block). K = Kq (Q channels, 1 product) +
// 512 (XT left channels, 2 products). Writes OUT8 (with bias on blade 0).
// ---------------------------------------------------------------------------
__global__ void __launch_bounds__(256, 1)
gemm_bil(const float* __restrict__ bias) {
    extern __shared__ __align__(1024) char smem[];
    uint32_t sb = s2u(smem);
    int tid = threadIdx.x, lane = tid & 31, wid = tid >> 5;
    int wm = wid & 3, wn = wid >> 2;

    int yb = blockIdx.y, g, rb;
    if      (yb < 8)   { g = 0; rb = yb; }
    else if (yb < 32)  { g = 1; rb = yb - 8; }
    else if (yb < 56)  { g = 2; rb = yb - 32; }
    else               { g = 3; rb = yb - 56; }
    int Kq, s, pb;
    size_t qo; int wo;
    if      (g == 0) { Kq = 2048; s = 1; pb = 0; qo = QOFF0; wo = WBOFF0; }
    else if (g == 1) { Kq = 3072; s = 3; pb = 1; qo = QOFF1; wo = WBOFF1; }
    else if (g == 2) { Kq = 3072; s = 3; pb = 4; qo = QOFF2; wo = WBOFF2; }
    else             { Kq = 2048; s = 1; pb = 7; qo = QOFF3; wo = WBOFF3; }
    int row0 = rb * 256, col0 = blockIdx.x * 128;
    const __half* Aq = g_Q + qo;
    const __half* Bq = g_WB + wo;
    const __half* Bl = g_WL + (size_t)g * WSLICE;

    int nch_q = Kq >> 6;
    int nch   = nch_q + 8;

    int a_rowb = wm * 64 + (lane & 15);
    int b_rowb = wn * 64 + (lane & 7) + ((lane >> 4) << 3);
    uint32_t a_colp = (uint32_t)((lane >> 4) << 4);
    uint32_t b_colp = (uint32_t)(((lane >> 3) & 1) << 4);
    uint32_t xmask  = (uint32_t)((lane & 7) << 4);

    float acc[4][8][4];
#pragma unroll
    for (int mt = 0; mt < 4; mt++)
#pragma unroll
        for (int nt = 0; nt < 8; nt++)
#pragma unroll
            for (int q = 0; q < 4; q++) acc[mt][nt][q] = 0.0f;

    auto load = [&](int buf, int ci) {
        uint32_t st = sb + buf * STAGE_BYTES;
        int kt = ci << 6;
        if (ci < nch_q) {
            // Q region: A = Q (single), B = WB
#pragma unroll
            for (int i = 0; i < 8; i++) {
                int idx = i * 256 + tid;
                int r = idx >> 3, c16 = idx & 7;
                uint32_t so = SWZ((uint32_t)((r << 7) + (c16 << 4)));
                cp16(st + so, Aq + (size_t)(row0 + r) * Kq + kt + (c16 << 3));
            }
#pragma unroll
            for (int i = 0; i < 4; i++) {
                int idx = i * 256 + tid;
                int r = idx >> 3, c16 = idx & 7;
                uint32_t so = SWZ((uint32_t)((r << 7) + (c16 << 4)));
                cp16(st + 65536u + so, Bq + (size_t)(col0 + r) * Kq + kt + (c16 << 3));
            }
        } else {
            // left region: A = XT[pb+j] hi/lo, B = WL[g]
            int kk = kt - Kq;
#pragma unroll
            for (int i = 0; i < 8; i++) {
                int idx = i * 256 + tid;
                int r = idx >> 3, c16 = idx & 7;
                uint32_t so = SWZ((uint32_t)((r << 7) + (c16 << 4)));
                int rr = row0 + r, bb, jj;
                if (s == 1) { bb = rr; jj = 0; } else { bb = rr / 3; jj = rr - bb * 3; }
                size_t go = (size_t)(pb + jj) * PLANE + (size_t)bb * 512 + kk + (c16 << 3);
                cp16(st + so,          g_XTh + go);
                cp16(st + 32768u + so, g_XTl + go);
            }
#pragma unroll
            for (int i = 0; i < 4; i++) {
                int idx = i * 256 + tid;
                int r = idx >> 3, c16 = idx & 7;
                uint32_t so = SWZ((uint32_t)((r << 7) + (c16 << 4)));
                cp16(st + 65536u + so, Bl + (size_t)(col0 + r) * 512 + kk + (c16 << 3));
            }
        }
    };

    load(0, 0);
    CP_COMMIT();
    for (int c = 0; c < nch; c++) {
        int buf = c & 1;
        if (c + 1 < nch) { load(buf ^ 1, c + 1); CP_COMMIT(); CP_WAIT1(); }
        else             { CP_WAIT0(); }
        __syncthreads();

        uint32_t st  = sb + buf * STAGE_BYTES;
        uint32_t sAh = st, sAl = st + 32768u, sB = st + 65536u;
        int two = (c >= nch_q);
#pragma unroll
        for (int ks = 0; ks < 4; ks++) {
            uint32_t acol = ((uint32_t)(ks << 5) | a_colp) ^ xmask;
            uint32_t bcol = ((uint32_t)(ks << 5) | b_colp) ^ xmask;
            uint32_t af[4][4], bf[4][4];
#pragma unroll
            for (int mt = 0; mt < 4; mt++)
                ldsm4(af[mt], sAh + (uint32_t)((a_rowb + mt * 16) << 7) + acol);
#pragma unroll
            for (int bt = 0; bt < 4; bt++)
                ldsm4(bf[bt], sB + (uint32_t)((b_rowb + bt * 16) << 7) + bcol);
#pragma unroll
            for (int mt = 0; mt < 4; mt++)
#pragma unroll
                for (int nt = 0; nt < 8; nt++)
                    mma_fp16(acc[mt][nt], af[mt], bf[nt >> 1][(nt & 1) * 2],
                             bf[nt >> 1][(nt & 1) * 2 + 1]);
            if (two) {
#pragma unroll
                for (int mt = 0; mt < 4; mt++)
                    ldsm4(af[mt], sAl + (uint32_t)((a_rowb + mt * 16) << 7) + acol);
#pragma unroll
                for (int mt = 0; mt < 4; mt++)
#pragma unroll
                    for (int nt = 0; nt < 8; nt++)
                        mma_fp16(acc[mt][nt], af[mt], bf[nt >> 1][(nt & 1) * 2],
                                 bf[nt >> 1][(nt & 1) * 2 + 1]);
            }
        }
        __syncthreads();
    }

    // epilogue: write OUT8 (bias on blade 0 == grade 0)
    int gr = row0 + wm * 64 + (lane >> 2);
    int gc = col0 + wn * 64 + (lane & 3) * 2;
    bool addb = (g == 0);
#pragma unroll
    for (int mt = 0; mt < 4; mt++) {
#pragma unroll
        for (int half = 0; half < 2; half++) {
            int r = gr + mt * 16 + half * 8;
            int bb, jj;
            if (s == 1) { bb = r; jj = 0; } else { bb = r / 3; jj = r - bb * 3; }
            float* base = g_OUT8 + (size_t)(pb + jj) * PLANE + (size_t)bb * 512;
#pragma unroll
            for (int nt = 0; nt < 8; nt++) {
                int cc = gc + nt * 8;
                float bx = 0.f, by = 0.f;
                if (addb) { bx = bias[cc]; by = bias[cc + 1]; }
                *(float2*)(base + cc) =
                    make_float2(acc[mt][nt][half * 2] + bx,
                                acc[mt][nt][half * 2 + 1] + by);
            }
        }
    }
}

// ---------------------------------------------------------------------------
// Elementwise kernels
// ---------------------------------------------------------------------------
__device__ __forceinline__ void hsplit(float v, __half* h, __half* l) {
    __half hh = __float2half_rn(v);
    *h = hh;
    *l = __float2half_rn(v - __half2float(hh));
}

__global__ void prep_x_kernel(const float* __restrict__ x) {
    int idx = blockIdx.x * 256 + threadIdx.x;
    const float4* x4 = (const float4*)x;
    float4 a = x4[idx * 2];
    float4 b = x4[idx * 2 + 1];
    float v[8] = {a.x, a.y, a.z, a.w, b.x, b.y, b.z, b.w};
#pragma unroll
    for (int i = 0; i < 8; i++) {
        __half h, l;
        hsplit(v[i], &h, &l);
        g_XTh[(size_t)i * PLANE + idx] = h;
        g_XTl[(size_t)i * PLANE + idx] = l;
    }
}

__global__ void prep_w_kernel(const float* __restrict__ weight,
                              const float* __restrict__ w_right,
                              const float* __restrict__ w_left) {
    int idx = blockIdx.x * 256 + threadIdx.x;
    if (idx < WBTOT) {
        int kb = idx >> 18, rem = idx & (WSLICE - 1);
        int m = rem >> 9, n = rem & 511;
        float v = weight[(size_t)(m * 512 + n) * 20 + c_porder[kb]];
        size_t d = (size_t)c_kb_base[kb] + (size_t)m * c_kb_K[kb] + n;
        g_WB[d] = __float2half_rn(v);
    } else if (idx < WBTOT + 4 * WSLICE) {
        int t = idx - WBTOT;
        int g = t >> 18, rem = t & (WSLICE - 1);
        int m = rem >> 9, n = rem & 511;
        float v = w_right[(size_t)(m * 512 + n) * 4 + g];
        size_t d = (size_t)g * WSLICE + m * 512 + n;
        hsplit(v, &g_WRh[d], &g_WRl[d]);
    } else {
        int t = idx - WBTOT - 4 * WSLICE;
        int g = t >> 18, rem = t & (WSLICE - 1);
        int m = rem >> 9, n = rem & 511;
        float v = w_left[(size_t)(m * 512 + n) * 4 + g];
        size_t d = (size_t)g * WSLICE + m * 512 + n;
        g_WL[d] = __float2half_rn(v);
    }
}

#define QW(off, val) g_Q[off] = __float2half_rn(val)

__global__ void qfill_kernel(const float* __restrict__ x,
                             const float* __restrict__ norm_a) {
    int idx = blockIdx.x * 256 + threadIdx.x;   // b*512 + n
    int b = idx >> 9, n = idx & 511;

    const float4* x4 = (const float4*)x;
    float4 xa = x4[idx * 2];
    float4 xb = x4[idx * 2 + 1];
    float x0 = xa.x, x1 = xa.y, x2 = xa.z, x3 = xa.w;
    float x4v = xb.x, x5 = xb.y, x6 = xb.z, x7 = xb.w;

    float r0 = g_XR[0 * PLANE + idx], r1 = g_XR[1 * PLANE + idx];
    float r2 = g_XR[2 * PLANE + idx], r3 = g_XR[3 * PLANE + idx];
    float r4 = g_XR[4 * PLANE + idx], r5 = g_XR[5 * PLANE + idx];
    float r6 = g_XR[6 * PLANE + idx], r7 = g_XR[7 * PLANE + idx];

    float nn[4];
    nn[0] = sqrtf(r0 * r0);
    nn[1] = sqrtf(r1 * r1 + r2 * r2 + r3 * r3);
    nn[2] = sqrtf(r4 * r4 + r5 * r5 + r6 * r6);
    nn[3] = sqrtf(r7 * r7);
    float f[4];
#pragma unroll
    for (int gg = 0; gg < 4; gg++) {
        float a = norm_a[n * 4 + gg];
        float sg = 1.0f / (1.0f + expf(-a));
        f[gg] = sg * (nn[gg] - 1.0f) + 1.0f + 1e-6f;
    }
    r0 /= f[0];
    r1 /= f[1]; r2 /= f[1]; r3 /= f[1];
    r4 /= f[2]; r5 /= f[2]; r6 /= f[2];
    r7 /= f[3];

    {
        size_t q = QOFF0 + (size_t)b * 2048 + n;
        QW(q,        x0 * r0);
        QW(q + 512,  x1 * r1 + x2 * r2 + x3 * r3);
        QW(q + 1024, -(x4v * r4 + x5 * r5 + x6 * r6));
        QW(q + 1536, -(x7 * r7));
    }
    {
        size_t q = QOFF1 + (size_t)(b * 3) * 3072 + n;
        QW(q + 0,    x0 * r1);
        QW(q + 512,  x1 * r0);
        QW(q + 1024, -x2 * r4 - x3 * r5);
        QW(q + 1536, x4v * r2 + x5 * r3);
        QW(q + 2048, -x6 * r7);
        QW(q + 2560, -x7 * r6);
        QW(q + 3072 + 0,    x0 * r2);
        QW(q + 3072 + 512,  x2 * r0);
        QW(q + 3072 + 1024, x1 * r4 - x3 * r6);
        QW(q + 3072 + 1536, -x4v * r1 + x6 * r3);
        QW(q + 3072 + 2048, x5 * r7);
        QW(q + 3072 + 2560, x7 * r5);
        QW(q + 6144 + 0,    x0 * r3);
        QW(q + 6144 + 512,  x3 * r0);
        QW(q + 6144 + 1024, x1 * r5 + x2 * r6);
        QW(q + 6144 + 1536, -x5 * r1 - x6 * r2);
        QW(q + 6144 + 2048, -x4v * r7);
        QW(q + 6144 + 2560, -x7 * r4);
    }
    {
        size_t q = QOFF2 + (size_t)(b * 3) * 3072 + n;
        QW(q + 0,    x0 * r4);
        QW(q + 512,  x1 * r2 - x2 * r1);
        QW(q + 1024, x3 * r7);
        QW(q + 1536, x4v * r0);
        QW(q + 2048, -x5 * r6 + x6 * r5);
        QW(q + 2560, x7 * r3);
        QW(q + 3072 + 0,    x0 * r5);
        QW(q + 3072 + 512,  x1 * r3 - x3 * r1);
        QW(q + 3072 + 1024, -x2 * r7);
        QW(q + 3072 + 1536, x5 * r0);
        QW(q + 3072 + 2048, x4v * r6 - x6 * r4);
        QW(q + 3072 + 2560, -x7 * r2);
        QW(q + 6144 + 0,    x0 * r6);
        QW(q + 6144 + 512,  x2 * r3 - x3 * r2);
        QW(q + 6144 + 1024, x1 * r7);
        QW(q + 6144 + 1536, x6 * r0);
        QW(q + 6144 + 2048, -x4v * r5 + x5 * r4);
        QW(q + 6144 + 2560, x7 * r1);
    }
    {
        size_t q = QOFF3 + (size_t)b * 2048 + n;
        QW(q,        x0 * r7);
        QW(q + 512,  x1 * r6 - x2 * r5 + x3 * r4);
        QW(q + 1024, x4v * r3 - x5 * r2 + x6 * r1);
        QW(q + 1536, x7 * r0);
    }
}

__global__ void merge_out_kernel(float* __restrict__ out) {
    int idx = blockIdx.x * 256 + threadIdx.x;
    const float sc = 0.70710678118654752440f;
    float4 lo, hi;
    lo.x = g_OUT8[0 * PLANE + idx] * sc;
    lo.y = g_OUT8[1 * PLANE + idx] * sc;
    lo.z = g_OUT8[2 * PLANE + idx] * sc;
    lo.w = g_OUT8[3 * PLANE + idx] * sc;
    hi.x = g_OUT8[4 * PLANE + idx] * sc;
    hi.y = g_OUT8[5 * PLANE + idx] * sc;
    hi.z = g_OUT8[6 * PLANE + idx] * sc;
    hi.w = g_OUT8[7 * PLANE + idx] * sc;
    float4* o4 = (float4*)out;
    o4[idx * 2]     = lo;
    o4[idx * 2 + 1] = hi;
}

// ---------------------------------------------------------------------------
extern "C" void kernel_launch(void* const* d_in, const int* in_sizes, int n_in,
                              void* d_out, int out_size) {
    const float* x       = (const float*)d_in[0];
    const float* weight  = (const float*)d_in[1];
    const float* w_right = (const float*)d_in[2];
    const float* w_left  = (const float*)d_in[3];
    const float* b_left  = (const float*)d_in[4];
    const float* norm_a  = (const float*)d_in[5];
    float* out = (float*)d_out;

    cudaFuncSetAttribute(gemm_xr,  cudaFuncAttributeMaxDynamicSharedMemorySize, SMEM_BYTES);
    cudaFuncSetAttribute(gemm_bil, cudaFuncAttributeMaxDynamicSharedMemorySize, SMEM_BYTES);

    prep_x_kernel<<<PLANE / 256, 256>>>(x);
    prep_w_kernel<<<(WBTOT + 8 * WSLICE) / 256, 256>>>(weight, w_right, w_left);

    gemm_xr<<<dim3(4, 8, 8), 256, SMEM_BYTES>>>();              // XR
    qfill_kernel<<<PLANE / 256, 256>>>(x, norm_a);              // gate + Q (fp16)
    gemm_bil<<<dim3(4, 64, 1), 256, SMEM_BYTES>>>(b_left);      // bilinear + left
    merge_out_kernel<<<PLANE / 256, 256>>>(out);
}

// round 13
// speedup vs baseline: 5.6586x; 1.1078x over previous
#include <cuda_runtime.h>
#include <cuda_fp16.h>
#include <cstdint>

// ============================================================================
// Cl(3,0) steerable geometric product layer — baseline-PTX tensor cores.
// fp16 mma.sync.m16n8k16.
//   XR GEMM:   A split hi/lo, B single        -> 2 products, 2-stage pipeline
//   bilinear+left GEMM: all single-product    -> 1 product,  3-stage pipeline
// CTA tile 256x128, warp tile 64x64, 8 warps.
// ============================================================================

#define BDIM   2048
#define NIN    512
#define PLANE  (BDIM * NIN)          // 1048576
#define WSLICE (512 * 512)           // 262144

#define QOFF0 0
#define QOFF1 4194304
#define QOFF2 23068672
#define QOFF3 41943040
#define QTOT  46137344

#define WBOFF0 0
#define WBOFF1 1048576
#define WBOFF2 2621440
#define WBOFF3 4194304
#define WBTOT  5242880

__constant__ int c_porder[20] = {0,4,10,16, 1,5,6,11,12,17, 2,7,8,13,14,18, 3,9,15,19};
__constant__ int c_grade[8]   = {0,1,1,1,2,2,2,3};
__constant__ int c_kb_base[20] = {
    WBOFF0+0, WBOFF0+512, WBOFF0+1024, WBOFF0+1536,
    WBOFF1+0, WBOFF1+512, WBOFF1+1024, WBOFF1+1536, WBOFF1+2048, WBOFF1+2560,
    WBOFF2+0, WBOFF2+512, WBOFF2+1024, WBOFF2+1536, WBOFF2+2048, WBOFF2+2560,
    WBOFF3+0, WBOFF3+512, WBOFF3+1024, WBOFF3+1536};
__constant__ int c_kb_K[20] = {2048,2048,2048,2048, 3072,3072,3072,3072,3072,3072,
                               3072,3072,3072,3072,3072,3072, 2048,2048,2048,2048};

__device__ __align__(256) __half g_XTh[8 * PLANE];
__device__ __align__(256) __half g_XTl[8 * PLANE];
__device__ __align__(256) __half g_WR [4 * WSLICE];
__device__ __align__(256) __half g_WL [4 * WSLICE];
__device__ __align__(256) __half g_WB [WBTOT];
__device__ __align__(256) __half g_Q  [QTOT];
__device__ float g_XR  [8 * PLANE];
__device__ float g_OUT8[8 * PLANE];

// ---------------------------------------------------------------------------
__device__ __forceinline__ uint32_t s2u(const void* p) {
    return (uint32_t)__cvta_generic_to_shared(p);
}
__device__ __forceinline__ void cp16(uint32_t dst, const void* src) {
    asm volatile("cp.async.cg.shared.global [%0], [%1], 16;\n" :: "r"(dst), "l"(src));
}
#define CP_COMMIT() asm volatile("cp.async.commit_group;\n" ::: "memory")
#define CP_WAIT1()  asm volatile("cp.async.wait_group 1;\n" ::: "memory")
#define CP_WAIT0()  asm volatile("cp.async.wait_group 0;\n" ::: "memory")

__device__ __forceinline__ void ldsm4(uint32_t* r, uint32_t addr) {
    asm volatile("ldmatrix.sync.aligned.m8n8.x4.shared.b16 {%0,%1,%2,%3}, [%4];"
                 : "=r"(r[0]), "=r"(r[1]), "=r"(r[2]), "=r"(r[3]) : "r"(addr));
}
__device__ __forceinline__ void mma_fp16(float* c, const uint32_t* a,
                                         uint32_t b0, uint32_t b1) {
    asm volatile(
        "mma.sync.aligned.m16n8k16.row.col.f32.f16.f16.f32 "
        "{%0,%1,%2,%3}, {%4,%5,%6,%7}, {%8,%9}, {%0,%1,%2,%3};"
        : "+f"(c[0]), "+f"(c[1]), "+f"(c[2]), "+f"(c[3])
        : "r"(a[0]), "r"(a[1]), "r"(a[2]), "r"(a[3]), "r"(b0), "r"(b1));
}

#define SWZ(o) ((o) ^ (((o) >> 3) & 0x70))

// XR: stage = Ah 32KB @0, Al 32KB @32768, B 16KB @65536 -> 80KB, 2 stages
#define XR_STAGE 81920u
#define XR_SMEM  163840
// BIL: stage = A 32KB @0, B 16KB @32768 -> 48KB, 3 stages
#define BIL_STAGE 49152u
#define BIL_SMEM  147456

// ---------------------------------------------------------------------------
// XR GEMM: XR[z] = (XTh[z]+XTl[z]) @ WR[g(z)], 2 products.
// grid (4, 8, 8): x=col/128, y=row/256, z=blade.
// ---------------------------------------------------------------------------
__global__ void __launch_bounds__(256, 1)
gemm_xr() {
    extern __shared__ __align__(1024) char smem[];
    uint32_t sb = s2u(smem);
    int tid = threadIdx.x, lane = tid & 31, wid = tid >> 5;
    int wm = wid & 3, wn = wid >> 2;

    int z = blockIdx.z, g = c_grade[z];
    int row0 = blockIdx.y * 256, col0 = blockIdx.x * 128;
    const __half* Ah = g_XTh + (size_t)z * PLANE;
    const __half* Al = g_XTl + (size_t)z * PLANE;
    const __half* B  = g_WR  + (size_t)g * WSLICE;

    int a_rowb = wm * 64 + (lane & 15);
    int b_rowb = wn * 64 + (lane & 7) + ((lane >> 4) << 3);
    uint32_t a_colp = (uint32_t)((lane >> 4) << 4);
    uint32_t b_colp = (uint32_t)(((lane >> 3) & 1) << 4);
    uint32_t xmask  = (uint32_t)((lane & 7) << 4);

    float acc[4][8][4];
#pragma unroll
    for (int mt = 0; mt < 4; mt++)
#pragma unroll
        for (int nt = 0; nt < 8; nt++)
#pragma unroll
            for (int q = 0; q < 4; q++) acc[mt][nt][q] = 0.0f;

    auto load = [&](int buf, int kt) {
        uint32_t st = sb + buf * XR_STAGE;
#pragma unroll
        for (int i = 0; i < 8; i++) {
            int idx = i * 256 + tid;
            int r = idx >> 3, c16 = idx & 7;
            uint32_t so = SWZ((uint32_t)((r << 7) + (c16 << 4)));
            size_t go = (size_t)(row0 + r) * 512 + kt + (c16 << 3);
            cp16(st + so,          Ah + go);
            cp16(st + 32768u + so, Al + go);
        }
#pragma unroll
        for (int i = 0; i < 4; i++) {
            int idx = i * 256 + tid;
            int r = idx >> 3, c16 = idx & 7;
            uint32_t so = SWZ((uint32_t)((r << 7) + (c16 << 4)));
            cp16(st + 65536u + so, B + (size_t)(col0 + r) * 512 + kt + (c16 << 3));
        }
    };

    load(0, 0);
    CP_COMMIT();
    const int nch = 8;
    for (int c = 0; c < nch; c++) {
        int buf = c & 1;
        if (c + 1 < nch) { load(buf ^ 1, (c + 1) << 6); CP_COMMIT(); CP_WAIT1(); }
        else             { CP_WAIT0(); }
        __syncthreads();

        uint32_t st  = sb + buf * XR_STAGE;
        uint32_t sAh = st, sAl = st + 32768u, sB = st + 65536u;
#pragma unroll
        for (int ks = 0; ks < 4; ks++) {
            uint32_t acol = ((uint32_t)(ks << 5) | a_colp) ^ xmask;
            uint32_t bcol = ((uint32_t)(ks << 5) | b_colp) ^ xmask;
            uint32_t af[4][4], bf[4][4];
#pragma unroll
            for (int mt = 0; mt < 4; mt++)
                ldsm4(af[mt], sAh + (uint32_t)((a_rowb + mt * 16) << 7) + acol);
#pragma unroll
            for (int bt = 0; bt < 4; bt++)
                ldsm4(bf[bt], sB + (uint32_t)((b_rowb + bt * 16) << 7) + bcol);
#pragma unroll
            for (int mt = 0; mt < 4; mt++)
#pragma unroll
                for (int nt = 0; nt < 8; nt++)
                    mma_fp16(acc[mt][nt], af[mt], bf[nt >> 1][(nt & 1) * 2],
                             bf[nt >> 1][(nt & 1) * 2 + 1]);
#pragma unroll
            for (int mt = 0; mt < 4; mt++)
                ldsm4(af[mt], sAl + (uint32_t)((a_rowb + mt * 16) << 7) + acol);
#pragma unroll
            for (int mt = 0; mt < 4; mt++)
#pragma unroll
                for (int nt = 0; nt < 8; nt++)
                    mma_fp16(acc[mt][nt], af[mt], bf[nt >> 1][(nt & 1) * 2],
                             bf[nt >> 1][(nt & 1) * 2 + 1]);
        }
        __syncthreads();
    }

    int gr = row0 + wm * 64 + (lane >> 2);
    int gc = col0 + wn * 64 + (lane & 3) * 2;
    float* base = g_XR + (size_t)z * PLANE;
#pragma unroll
    for (int mt = 0; mt < 4; mt++) {
        int r0 = gr + mt * 16;
#pragma unroll
        for (int nt = 0; nt < 8; nt++) {
            int cc = gc + nt * 8;
            *(float2*)(base + (size_t)r0 * 512 + cc) =
                make_float2(acc[mt][nt][0], acc[mt][nt][1]);
            *(float2*)(base + (size_t)(r0 + 8) * 512 + cc) =
                make_float2(acc[mt][nt][2], acc[mt][nt][3]);
        }
    }
}

// ---------------------------------------------------------------------------
// Fused bilinear + left GEMM, all single-product, 3-stage pipeline.
// grid (4, 64): y -> (grade, row-block). K = Kq (Q channels) + 512 (XT left).
// ---------------------------------------------------------------------------
__global__ void __launch_bounds__(256, 1)
gemm_bil(const float* __restrict__ bias) {
    extern __shared__ __align__(1024) char smem[];
    uint32_t sb = s2u(smem);
    int tid = threadIdx.x, lane = tid & 31, wid = tid >> 5;
    int wm = wid & 3, wn = wid >> 2;

    int yb = blockIdx.y, g, rb;
    if      (yb < 8)   { g = 0; rb = yb; }
    else if (yb < 32)  { g = 1; rb = yb - 8; }
    else if (yb < 56)  { g = 2; rb = yb - 32; }
    else               { g = 3; rb = yb - 56; }
    int Kq, s, pb;
    size_t qo; int wo;
    if      (g == 0) { Kq = 2048; s = 1; pb = 0; qo = QOFF0; wo = WBOFF0; }
    else if (g == 1) { Kq = 3072; s = 3; pb = 1; qo = QOFF1; wo = WBOFF1; }
    else if (g == 2) { Kq = 3072; s = 3; pb = 4; qo = QOFF2; wo = WBOFF2; }
    else             { Kq = 2048; s = 1; pb = 7; qo = QOFF3; wo = WBOFF3; }
    int row0 = rb * 256, col0 = blockIdx.x * 128;
    const __half* Aq = g_Q + qo;
    const __half* Bq = g_WB + wo;
    const __half* Bl = g_WL + (size_t)g * WSLICE;

    int nch_q = Kq >> 6;
    int nch   = nch_q + 8;

    int a_rowb = wm * 64 + (lane & 15);
    int b_rowb = wn * 64 + (lane & 7) + ((lane >> 4) << 3);
    uint32_t a_colp = (uint32_t)((lane >> 4) << 4);
    uint32_t b_colp = (uint32_t)(((lane >> 3) & 1) << 4);
    uint32_t xmask  = (uint32_t)((lane & 7) << 4);

    float acc[4][8][4];
#pragma unroll
    for (int mt = 0; mt < 4; mt++)
#pragma unroll
        for (int nt = 0; nt < 8; nt++)
#pragma unroll
            for (int q = 0; q < 4; q++) acc[mt][nt][q] = 0.0f;

    auto load = [&](int buf, int ci) {
        uint32_t st = sb + buf * BIL_STAGE;
        int kt = ci << 6;
        if (ci < nch_q) {
#pragma unroll
            for (int i = 0; i < 8; i++) {
                int idx = i * 256 + tid;
                int r = idx >> 3, c16 = idx & 7;
                uint32_t so = SWZ((uint32_t)((r << 7) + (c16 << 4)));
                cp16(st + so, Aq + (size_t)(row0 + r) * Kq + kt + (c16 << 3));
            }
#pragma unroll
            for (int i = 0; i < 4; i++) {
                int idx = i * 256 + tid;
                int r = idx >> 3, c16 = idx & 7;
                uint32_t so = SWZ((uint32_t)((r << 7) + (c16 << 4)));
                cp16(st + 32768u + so, Bq + (size_t)(col0 + r) * Kq + kt + (c16 << 3));
            }
        } else {
            int kk = kt - Kq;
#pragma unroll
            for (int i = 0; i < 8; i++) {
                int idx = i * 256 + tid;
                int r = idx >> 3, c16 = idx & 7;
                uint32_t so = SWZ((uint32_t)((r << 7) + (c16 << 4)));
                int rr = row0 + r, bb, jj;
                if (s == 1) { bb = rr; jj = 0; } else { bb = rr / 3; jj = rr - bb * 3; }
                cp16(st + so, g_XTh + (size_t)(pb + jj) * PLANE
                                    + (size_t)bb * 512 + kk + (c16 << 3));
            }
#pragma unroll
            for (int i = 0; i < 4; i++) {
                int idx = i * 256 + tid;
                int r = idx >> 3, c16 = idx & 7;
                uint32_t so = SWZ((uint32_t)((r << 7) + (c16 << 4)));
                cp16(st + 32768u + so, Bl + (size_t)(col0 + r) * 512 + kk + (c16 << 3));
            }
        }
    };

    load(0, 0); CP_COMMIT();
    load(1, 1); CP_COMMIT();
    for (int c = 0; c < nch; c++) {
        if (c + 1 < nch) CP_WAIT1(); else CP_WAIT0();
        __syncthreads();
        if (c + 2 < nch) {
            int nb = (c + 2) % 3;
            load(nb, c + 2);
            CP_COMMIT();
        }

        uint32_t st = sb + (uint32_t)(c % 3) * BIL_STAGE;
        uint32_t sA = st, sB = st + 32768u;
#pragma unroll
        for (int ks = 0; ks < 4; ks++) {
            uint32_t acol = ((uint32_t)(ks << 5) | a_colp) ^ xmask;
            uint32_t bcol = ((uint32_t)(ks << 5) | b_colp) ^ xmask;
            uint32_t af[4][4], bf[4][4];
#pragma unroll
            for (int mt = 0; mt < 4; mt++)
                ldsm4(af[mt], sA + (uint32_t)((a_rowb + mt * 16) << 7) + acol);
#pragma unroll
            for (int bt = 0; bt < 4; bt++)
                ldsm4(bf[bt], sB + (uint32_t)((b_rowb + bt * 16) << 7) + bcol);
#pragma unroll
            for (int mt = 0; mt < 4; mt++)
#pragma unroll
                for (int nt = 0; nt < 8; nt++)
                    mma_fp16(acc[mt][nt], af[mt], bf[nt >> 1][(nt & 1) * 2],
                             bf[nt >> 1][(nt & 1) * 2 + 1]);
        }
        __syncthreads();
    }

    int gr = row0 + wm * 64 + (lane >> 2);
    int gc = col0 + wn * 64 + (lane & 3) * 2;
    bool addb = (g == 0);
#pragma unroll
    for (int mt = 0; mt < 4; mt++) {
#pragma unroll
        for (int half = 0; half < 2; half++) {
            int r = gr + mt * 16 + half * 8;
            int bb, jj;
            if (s == 1) { bb = r; jj = 0; } else { bb = r / 3; jj = r - bb * 3; }
            float* base = g_OUT8 + (size_t)(pb + jj) * PLANE + (size_t)bb * 512;
#pragma unroll
            for (int nt = 0; nt < 8; nt++) {
                int cc = gc + nt * 8;
                float bx = 0.f, by = 0.f;
                if (addb) { bx = bias[cc]; by = bias[cc + 1]; }
                *(float2*)(base + cc) =
                    make_float2(acc[mt][nt][half * 2] + bx,
                                acc[mt][nt][half * 2 + 1] + by);
            }
        }
    }
}

// ---------------------------------------------------------------------------
// Elementwise kernels
// ---------------------------------------------------------------------------
__device__ __forceinline__ void hsplit(float v, __half* h, __half* l) {
    __half hh = __float2half_rn(v);
    *h = hh;
    *l = __float2half_rn(v - __half2float(hh));
}

__global__ void prep_x_kernel(const float* __restrict__ x) {
    int idx = blockIdx.x * 256 + threadIdx.x;
    const float4* x4 = (const float4*)x;
    float4 a = x4[idx * 2];
    float4 b = x4[idx * 2 + 1];
    float v[8] = {a.x, a.y, a.z, a.w, b.x, b.y, b.z, b.w};
#pragma unroll
    for (int i = 0; i < 8; i++) {
        __half h, l;
        hsplit(v[i], &h, &l);
        g_XTh[(size_t)i * PLANE + idx] = h;
        g_XTl[(size_t)i * PLANE + idx] = l;
    }
}

__global__ void prep_w_kernel(const float* __restrict__ weight,
                              const float* __restrict__ w_right,
                              const float* __restrict__ w_left) {
    int idx = blockIdx.x * 256 + threadIdx.x;
    if (idx < WBTOT) {
        int kb = idx >> 18, rem = idx & (WSLICE - 1);
        int m = rem >> 9, n = rem & 511;
        float v = weight[(size_t)(m * 512 + n) * 20 + c_porder[kb]];
        size_t d = (size_t)c_kb_base[kb] + (size_t)m * c_kb_K[kb] + n;
        g_WB[d] = __float2half_rn(v);
    } else if (idx < WBTOT + 4 * WSLICE) {
        int t = idx - WBTOT;
        int g = t >> 18, rem = t & (WSLICE - 1);
        int m = rem >> 9, n = rem & 511;
        g_WR[(size_t)g * WSLICE + m * 512 + n] =
            __float2half_rn(w_right[(size_t)(m * 512 + n) * 4 + g]);
    } else {
        int t = idx - WBTOT - 4 * WSLICE;
        int g = t >> 18, rem = t & (WSLICE - 1);
        int m = rem >> 9, n = rem & 511;
        g_WL[(size_t)g * WSLICE + m * 512 + n] =
            __float2half_rn(w_left[(size_t)(m * 512 + n) * 4 + g]);
    }
}

#define QW(off, val) g_Q[off] = __float2half_rn(val)

__global__ void qfill_kernel(const float* __restrict__ norm_a) {
    int idx = blockIdx.x * 256 + threadIdx.x;   // b*512 + n
    int b = idx >> 9, n = idx & 511;

    // reconstruct x from hi+lo planes (exact to ~2^-22)
    float xv[8];
#pragma unroll
    for (int i = 0; i < 8; i++)
        xv[i] = __half2float(g_XTh[(size_t)i * PLANE + idx]) +
                __half2float(g_XTl[(size_t)i * PLANE + idx]);
    float x0 = xv[0], x1 = xv[1], x2 = xv[2], x3 = xv[3];
    float x4v = xv[4], x5 = xv[5], x6 = xv[6], x7 = xv[7];

    float r0 = g_XR[0 * PLANE + idx], r1 = g_XR[1 * PLANE + idx];
    float r2 = g_XR[2 * PLANE + idx], r3 = g_XR[3 * PLANE + idx];
    float r4 = g_XR[4 * PLANE + idx], r5 = g_XR[5 * PLANE + idx];
    float r6 = g_XR[6 * PLANE + idx], r7 = g_XR[7 * PLANE + idx];

    float nn[4];
    nn[0] = sqrtf(r0 * r0);
    nn[1] = sqrtf(r1 * r1 + r2 * r2 + r3 * r3);
    nn[2] = sqrtf(r4 * r4 + r5 * r5 + r6 * r6);
    nn[3] = sqrtf(r7 * r7);
    float f[4];
#pragma unroll
    for (int gg = 0; gg < 4; gg++) {
        float a = norm_a[n * 4 + gg];
        float sg = 1.0f / (1.0f + expf(-a));
        f[gg] = sg * (nn[gg] - 1.0f) + 1.0f + 1e-6f;
    }
    r0 /= f[0];
    r1 /= f[1]; r2 /= f[1]; r3 /= f[1];
    r4 /= f[2]; r5 /= f[2]; r6 /= f[2];
    r7 /= f[3];

    {
        size_t q = QOFF0 + (size_t)b * 2048 + n;
        QW(q,        x0 * r0);
        QW(q + 512,  x1 * r1 + x2 * r2 + x3 * r3);
        QW(q + 1024, -(x4v * r4 + x5 * r5 + x6 * r6));
        QW(q + 1536, -(x7 * r7));
    }
    {
        size_t q = QOFF1 + (size_t)(b * 3) * 3072 + n;
        QW(q + 0,    x0 * r1);
        QW(q + 512,  x1 * r0);
        QW(q + 1024, -x2 * r4 - x3 * r5);
        QW(q + 1536, x4v * r2 + x5 * r3);
        QW(q + 2048, -x6 * r7);
        QW(q + 2560, -x7 * r6);
        QW(q + 3072 + 0,    x0 * r2);
        QW(q + 3072 + 512,  x2 * r0);
        QW(q + 3072 + 1024, x1 * r4 - x3 * r6);
        QW(q + 3072 + 1536, -x4v * r1 + x6 * r3);
        QW(q + 3072 + 2048, x5 * r7);
        QW(q + 3072 + 2560, x7 * r5);
        QW(q + 6144 + 0,    x0 * r3);
        QW(q + 6144 + 512,  x3 * r0);
        QW(q + 6144 + 1024, x1 * r5 + x2 * r6);
        QW(q + 6144 + 1536, -x5 * r1 - x6 * r2);
        QW(q + 6144 + 2048, -x4v * r7);
        QW(q + 6144 + 2560, -x7 * r4);
    }
    {
        size_t q = QOFF2 + (size_t)(b * 3) * 3072 + n;
        QW(q + 0,    x0 * r4);
        QW(q + 512,  x1 * r2 - x2 * r1);
        QW(q + 1024, x3 * r7);
        QW(q + 1536, x4v * r0);
        QW(q + 2048, -x5 * r6 + x6 * r5);
        QW(q + 2560, x7 * r3);
        QW(q + 3072 + 0,    x0 * r5);
        QW(q + 3072 + 512,  x1 * r3 - x3 * r1);
        QW(q + 3072 + 1024, -x2 * r7);
        QW(q + 3072 + 1536, x5 * r0);
        QW(q + 3072 + 2048, x4v * r6 - x6 * r4);
        QW(q + 3072 + 2560, -x7 * r2);
        QW(q + 6144 + 0,    x0 * r6);
        QW(q + 6144 + 512,  x2 * r3 - x3 * r2);
        QW(q + 6144 + 1024, x1 * r7);
        QW(q + 6144 + 1536, x6 * r0);
        QW(q + 6144 + 2048, -x4v * r5 + x5 * r4);
        QW(q + 6144 + 2560, x7 * r1);
    }
    {
        size_t q = QOFF3 + (size_t)b * 2048 + n;
        QW(q,        x0 * r7);
        QW(q + 512,  x1 * r6 - x2 * r5 + x3 * r4);
        QW(q + 1024, x4v * r3 - x5 * r2 + x6 * r1);
        QW(q + 1536, x7 * r0);
    }
}

__global__ void merge_out_kernel(float* __restrict__ out) {
    int idx = blockIdx.x * 256 + threadIdx.x;
    const float sc = 0.70710678118654752440f;
    float4 lo, hi;
    lo.x = g_OUT8[0 * PLANE + idx] * sc;
    lo.y = g_OUT8[1 * PLANE + idx] * sc;
    lo.z = g_OUT8[2 * PLANE + idx] * sc;
    lo.w = g_OUT8[3 * PLANE + idx] * sc;
    hi.x = g_OUT8[4 * PLANE + idx] * sc;
    hi.y = g_OUT8[5 * PLANE + idx] * sc;
    hi.z = g_OUT8[6 * PLANE + idx] * sc;
    hi.w = g_OUT8[7 * PLANE + idx] * sc;
    float4* o4 = (float4*)out;
    o4[idx * 2]     = lo;
    o4[idx * 2 + 1] = hi;
}

// ---------------------------------------------------------------------------
extern "C" void kernel_launch(void* const* d_in, const int* in_sizes, int n_in,
                              void* d_out, int out_size) {
    const float* x       = (const float*)d_in[0];
    const float* weight  = (const float*)d_in[1];
    const float* w_right = (const float*)d_in[2];
    const float* w_left  = (const float*)d_in[3];
    const float* b_left  = (const float*)d_in[4];
    const float* norm_a  = (const float*)d_in[5];
    float* out = (float*)d_out;

    cudaFuncSetAttribute(gemm_xr,  cudaFuncAttributeMaxDynamicSharedMemorySize, XR_SMEM);
    cudaFuncSetAttribute(gemm_bil, cudaFuncAttributeMaxDynamicSharedMemorySize, BIL_SMEM);

    prep_x_kernel<<<PLANE / 256, 256>>>(x);
    prep_w_kernel<<<(WBTOT + 8 * WSLICE) / 256, 256>>>(weight, w_right, w_left);

    gemm_xr<<<dim3(4, 8, 8), 256, XR_SMEM>>>();                 // XR (2 products)
    qfill_kernel<<<PLANE / 256, 256>>>(norm_a);                 // gate + Q (fp16)
    gemm_bil<<<dim3(4, 64, 1), 256, BIL_SMEM>>>(b_left);        // bilinear + left
    merge_out_kernel<<<PLANE / 256, 256>>>(out);
}

// round 14
// speedup vs baseline: 6.2147x; 1.0983x over previous
#include <cuda_runtime.h>
#include <cuda_fp16.h>
#include <cstdint>

// ============================================================================
// Cl(3,0) steerable geometric product layer — baseline-PTX tensor cores.
// fp16 mma.sync.m16n8k16.
//   gemm_xr  : A split hi/lo, B single (2 products), persistent 128x128 tiles
//   gemm_bil : bilinear+left, single product, persistent 128x128 tiles,
//              longest-first scheduling, 3-stage cp.async
// 2 CTAs/SM (96KB smem, 256 thr, warp tile 64x32).
// ============================================================================

#define BDIM   2048
#define NIN    512
#define PLANE  (BDIM * NIN)
#define WSLICE (512 * 512)

#define QOFF0 0
#define QOFF1 4194304
#define QOFF2 23068672
#define QOFF3 41943040
#define QTOT  46137344

#define WBOFF0 0
#define WBOFF1 1048576
#define WBOFF2 2621440
#define WBOFF3 4194304
#define WBTOT  5242880

__constant__ int c_porder[20] = {0,4,10,16, 1,5,6,11,12,17, 2,7,8,13,14,18, 3,9,15,19};
__constant__ int c_grade[8]   = {0,1,1,1,2,2,2,3};
__constant__ int c_kb_base[20] = {
    WBOFF0+0, WBOFF0+512, WBOFF0+1024, WBOFF0+1536,
    WBOFF1+0, WBOFF1+512, WBOFF1+1024, WBOFF1+1536, WBOFF1+2048, WBOFF1+2560,
    WBOFF2+0, WBOFF2+512, WBOFF2+1024, WBOFF2+1536, WBOFF2+2048, WBOFF2+2560,
    WBOFF3+0, WBOFF3+512, WBOFF3+1024, WBOFF3+1536};
__constant__ int c_kb_K[20] = {2048,2048,2048,2048, 3072,3072,3072,3072,3072,3072,
                               3072,3072,3072,3072,3072,3072, 2048,2048,2048,2048};

__device__ __align__(256) __half g_XTh[8 * PLANE];
__device__ __align__(256) __half g_XTl[8 * PLANE];
__device__ __align__(256) __half g_WR [4 * WSLICE];
__device__ __align__(256) __half g_WL [4 * WSLICE];
__device__ __align__(256) __half g_WB [WBTOT];
__device__ __align__(256) __half g_Q  [QTOT];
__device__ float g_XR  [8 * PLANE];
__device__ float g_OUT8[8 * PLANE];
__device__ int   g_cnt_xr;
__device__ int   g_cnt_bil;

// ---------------------------------------------------------------------------
__device__ __forceinline__ uint32_t s2u(const void* p) {
    return (uint32_t)__cvta_generic_to_shared(p);
}
__device__ __forceinline__ void cp16(uint32_t dst, const void* src) {
    asm volatile("cp.async.cg.shared.global [%0], [%1], 16;\n" :: "r"(dst), "l"(src));
}
#define CP_COMMIT() asm volatile("cp.async.commit_group;\n" ::: "memory")
#define CP_WAIT1()  asm volatile("cp.async.wait_group 1;\n" ::: "memory")
#define CP_WAIT0()  asm volatile("cp.async.wait_group 0;\n" ::: "memory")

__device__ __forceinline__ void ldsm4(uint32_t* r, uint32_t addr) {
    asm volatile("ldmatrix.sync.aligned.m8n8.x4.shared.b16 {%0,%1,%2,%3}, [%4];"
                 : "=r"(r[0]), "=r"(r[1]), "=r"(r[2]), "=r"(r[3]) : "r"(addr));
}
__device__ __forceinline__ void mma_fp16(float* c, const uint32_t* a,
                                         uint32_t b0, uint32_t b1) {
    asm volatile(
        "mma.sync.aligned.m16n8k16.row.col.f32.f16.f16.f32 "
        "{%0,%1,%2,%3}, {%4,%5,%6,%7}, {%8,%9}, {%0,%1,%2,%3};"
        : "+f"(c[0]), "+f"(c[1]), "+f"(c[2]), "+f"(c[3])
        : "r"(a[0]), "r"(a[1]), "r"(a[2]), "r"(a[3]), "r"(b0), "r"(b1));
}

#define SWZ(o) ((o) ^ (((o) >> 3) & 0x70))

// XR: stage = Ah 16KB + Al 16KB + B 16KB = 48KB, 2 stages = 96KB
#define XR_STAGE 49152u
// BIL: stage = A 16KB + B 16KB = 32KB, 3 stages = 96KB
#define BIL_STAGE 32768u
#define GSMEM 98304

#define NSM2 296   // 148 SMs x 2 CTAs

// ---------------------------------------------------------------------------
// XR GEMM (persistent): XR[z] = (XTh[z]+XTl[z]) @ WR[g(z)], 2 products.
// 512 tiles of 128x128.
// ---------------------------------------------------------------------------
__global__ void __launch_bounds__(256, 2)
gemm_xr() {
    extern __shared__ __align__(1024) char smem[];
    __shared__ int s_t;
    uint32_t sb = s2u(smem);
    int tid = threadIdx.x, lane = tid & 31, wid = tid >> 5;
    int wm = wid & 1, wn = wid >> 1;          // 2M x 4N

    int a_rowb = wm * 64 + (lane & 15);
    int b_rowb = wn * 32 + (lane & 7) + ((lane >> 4) << 3);
    uint32_t a_colp = (uint32_t)((lane >> 4) << 4);
    uint32_t b_colp = (uint32_t)(((lane >> 3) & 1) << 4);
    uint32_t xmask  = (uint32_t)((lane & 7) << 4);

    for (;;) {
        if (tid == 0) s_t = atomicAdd(&g_cnt_xr, 1);
        __syncthreads();
        int t = s_t;
        __syncthreads();
        if (t >= 512) break;

        int z = t & 7, r2 = t >> 3;
        int cb = r2 & 3, mb = r2 >> 2;
        int row0 = mb * 128, col0 = cb * 128;
        int g = c_grade[z];
        const __half* Ah = g_XTh + (size_t)z * PLANE;
        const __half* Al = g_XTl + (size_t)z * PLANE;
        const __half* B  = g_WR  + (size_t)g * WSLICE;

        float acc[4][4][4];
#pragma unroll
        for (int mt = 0; mt < 4; mt++)
#pragma unroll
            for (int nt = 0; nt < 4; nt++)
#pragma unroll
                for (int q = 0; q < 4; q++) acc[mt][nt][q] = 0.0f;

        auto load = [&](int buf, int kt) {
            uint32_t st = sb + buf * XR_STAGE;
#pragma unroll
            for (int i = 0; i < 4; i++) {
                int u = i * 256 + tid;
                int r = u >> 3, c16 = u & 7;
                uint32_t so = SWZ((uint32_t)((r << 7) + (c16 << 4)));
                size_t go = (size_t)(row0 + r) * 512 + kt + (c16 << 3);
                cp16(st + so,          Ah + go);
                cp16(st + 16384u + so, Al + go);
                cp16(st + 32768u + so, B + (size_t)(col0 + r) * 512 + kt + (c16 << 3));
            }
        };

        load(0, 0);
        CP_COMMIT();
        const int nch = 8;
        for (int c = 0; c < nch; c++) {
            int buf = c & 1;
            if (c + 1 < nch) { load(buf ^ 1, (c + 1) << 6); CP_COMMIT(); CP_WAIT1(); }
            else             { CP_WAIT0(); }
            __syncthreads();

            uint32_t st  = sb + buf * XR_STAGE;
            uint32_t sAh = st, sAl = st + 16384u, sB = st + 32768u;
#pragma unroll
            for (int ks = 0; ks < 4; ks++) {
                uint32_t acol = ((uint32_t)(ks << 5) | a_colp) ^ xmask;
                uint32_t bcol = ((uint32_t)(ks << 5) | b_colp) ^ xmask;
                uint32_t af[4][4], bf[2][4];
#pragma unroll
                for (int mt = 0; mt < 4; mt++)
                    ldsm4(af[mt], sAh + (uint32_t)((a_rowb + mt * 16) << 7) + acol);
#pragma unroll
                for (int bt = 0; bt < 2; bt++)
                    ldsm4(bf[bt], sB + (uint32_t)((b_rowb + bt * 16) << 7) + bcol);
#pragma unroll
                for (int mt = 0; mt < 4; mt++)
#pragma unroll
                    for (int nt = 0; nt < 4; nt++)
                        mma_fp16(acc[mt][nt], af[mt], bf[nt >> 1][(nt & 1) * 2],
                                 bf[nt >> 1][(nt & 1) * 2 + 1]);
#pragma unroll
                for (int mt = 0; mt < 4; mt++)
                    ldsm4(af[mt], sAl + (uint32_t)((a_rowb + mt * 16) << 7) + acol);
#pragma unroll
                for (int mt = 0; mt < 4; mt++)
#pragma unroll
                    for (int nt = 0; nt < 4; nt++)
                        mma_fp16(acc[mt][nt], af[mt], bf[nt >> 1][(nt & 1) * 2],
                                 bf[nt >> 1][(nt & 1) * 2 + 1]);
            }
            __syncthreads();
        }

        int gr = row0 + wm * 64 + (lane >> 2);
        int gc = col0 + wn * 32 + (lane & 3) * 2;
        float* base = g_XR + (size_t)z * PLANE;
#pragma unroll
        for (int mt = 0; mt < 4; mt++) {
            int r0 = gr + mt * 16;
#pragma unroll
            for (int nt = 0; nt < 4; nt++) {
                int cc = gc + nt * 8;
                *(float2*)(base + (size_t)r0 * 512 + cc) =
                    make_float2(acc[mt][nt][0], acc[mt][nt][1]);
                *(float2*)(base + (size_t)(r0 + 8) * 512 + cc) =
                    make_float2(acc[mt][nt][2], acc[mt][nt][3]);
            }
        }
    }
}

// ---------------------------------------------------------------------------
// Fused bilinear + left GEMM (persistent, longest-first).
// 512 tiles of 128x128: t<192 g1, <384 g2, <448 g0, else g3.
// ---------------------------------------------------------------------------
__global__ void __launch_bounds__(256, 2)
gemm_bil(const float* __restrict__ bias) {
    extern __shared__ __align__(1024) char smem[];
    __shared__ int s_t;
    uint32_t sb = s2u(smem);
    int tid = threadIdx.x, lane = tid & 31, wid = tid >> 5;
    int wm = wid & 1, wn = wid >> 1;

    int a_rowb = wm * 64 + (lane & 15);
    int b_rowb = wn * 32 + (lane & 7) + ((lane >> 4) << 3);
    uint32_t a_colp = (uint32_t)((lane >> 4) << 4);
    uint32_t b_colp = (uint32_t)(((lane >> 3) & 1) << 4);
    uint32_t xmask  = (uint32_t)((lane & 7) << 4);

    for (;;) {
        if (tid == 0) s_t = atomicAdd(&g_cnt_bil, 1);
        __syncthreads();
        int t = s_t;
        __syncthreads();
        if (t >= 512) break;

        int g, u;
        if      (t < 192) { g = 1; u = t; }
        else if (t < 384) { g = 2; u = t - 192; }
        else if (t < 448) { g = 0; u = t - 384; }
        else              { g = 3; u = t - 448; }
        int rb = u >> 2, cb = u & 3;

        int Kq, s, pb;
        size_t qo; int wo;
        if      (g == 0) { Kq = 2048; s = 1; pb = 0; qo = QOFF0; wo = WBOFF0; }
        else if (g == 1) { Kq = 3072; s = 3; pb = 1; qo = QOFF1; wo = WBOFF1; }
        else if (g == 2) { Kq = 3072; s = 3; pb = 4; qo = QOFF2; wo = WBOFF2; }
        else             { Kq = 2048; s = 1; pb = 7; qo = QOFF3; wo = WBOFF3; }
        int row0 = rb * 128, col0 = cb * 128;
        const __half* Aq = g_Q + qo;
        const __half* Bq = g_WB + wo;
        const __half* Bl = g_WL + (size_t)g * WSLICE;

        int nch_q = Kq >> 6;
        int nch   = nch_q + 8;

        float acc[4][4][4];
#pragma unroll
        for (int mt = 0; mt < 4; mt++)
#pragma unroll
            for (int nt = 0; nt < 4; nt++)
#pragma unroll
                for (int q = 0; q < 4; q++) acc[mt][nt][q] = 0.0f;

        auto load = [&](int buf, int ci) {
            uint32_t st = sb + buf * BIL_STAGE;
            int kt = ci << 6;
            if (ci < nch_q) {
#pragma unroll
                for (int i = 0; i < 4; i++) {
                    int v = i * 256 + tid;
                    int r = v >> 3, c16 = v & 7;
                    uint32_t so = SWZ((uint32_t)((r << 7) + (c16 << 4)));
                    cp16(st + so, Aq + (size_t)(row0 + r) * Kq + kt + (c16 << 3));
                    cp16(st + 16384u + so,
                         Bq + (size_t)(col0 + r) * Kq + kt + (c16 << 3));
                }
            } else {
                int kk = kt - Kq;
#pragma unroll
                for (int i = 0; i < 4; i++) {
                    int v = i * 256 + tid;
                    int r = v >> 3, c16 = v & 7;
                    uint32_t so = SWZ((uint32_t)((r << 7) + (c16 << 4)));
                    int rr = row0 + r, bb, jj;
                    if (s == 1) { bb = rr; jj = 0; }
                    else        { bb = rr / 3; jj = rr - bb * 3; }
                    cp16(st + so, g_XTh + (size_t)(pb + jj) * PLANE
                                        + (size_t)bb * 512 + kk + (c16 << 3));
                    cp16(st + 16384u + so,
                         Bl + (size_t)(col0 + r) * 512 + kk + (c16 << 3));
                }
            }
        };

        load(0, 0); CP_COMMIT();
        load(1, 1); CP_COMMIT();
        for (int c = 0; c < nch; c++) {
            if (c + 1 < nch) CP_WAIT1(); else CP_WAIT0();
            __syncthreads();
            if (c + 2 < nch) { load((c + 2) % 3, c + 2); CP_COMMIT(); }

            uint32_t st = sb + (uint32_t)(c % 3) * BIL_STAGE;
            uint32_t sA = st, sB = st + 16384u;
#pragma unroll
            for (int ks = 0; ks < 4; ks++) {
                uint32_t acol = ((uint32_t)(ks << 5) | a_colp) ^ xmask;
                uint32_t bcol = ((uint32_t)(ks << 5) | b_colp) ^ xmask;
                uint32_t af[4][4], bf[2][4];
#pragma unroll
                for (int mt = 0; mt < 4; mt++)
                    ldsm4(af[mt], sA + (uint32_t)((a_rowb + mt * 16) << 7) + acol);
#pragma unroll
                for (int bt = 0; bt < 2; bt++)
                    ldsm4(bf[bt], sB + (uint32_t)((b_rowb + bt * 16) << 7) + bcol);
#pragma unroll
                for (int mt = 0; mt < 4; mt++)
#pragma unroll
                    for (int nt = 0; nt < 4; nt++)
                        mma_fp16(acc[mt][nt], af[mt], bf[nt >> 1][(nt & 1) * 2],
                                 bf[nt >> 1][(nt & 1) * 2 + 1]);
            }
            __syncthreads();
        }

        int gr = row0 + wm * 64 + (lane >> 2);
        int gc = col0 + wn * 32 + (lane & 3) * 2;
        bool addb = (g == 0);
#pragma unroll
        for (int mt = 0; mt < 4; mt++) {
#pragma unroll
            for (int half = 0; half < 2; half++) {
                int r = gr + mt * 16 + half * 8;
                int bb, jj;
                if (s == 1) { bb = r; jj = 0; } else { bb = r / 3; jj = r - bb * 3; }
                float* base = g_OUT8 + (size_t)(pb + jj) * PLANE + (size_t)bb * 512;
#pragma unroll
                for (int nt = 0; nt < 4; nt++) {
                    int cc = gc + nt * 8;
                    float bx = 0.f, by = 0.f;
                    if (addb) { bx = bias[cc]; by = bias[cc + 1]; }
                    *(float2*)(base + cc) =
                        make_float2(acc[mt][nt][half * 2] + bx,
                                    acc[mt][nt][half * 2 + 1] + by);
                }
            }
        }
    }
}

// ---------------------------------------------------------------------------
// Elementwise kernels
// ---------------------------------------------------------------------------
__device__ __forceinline__ void hsplit(float v, __half* h, __half* l) {
    __half hh = __float2half_rn(v);
    *h = hh;
    *l = __float2half_rn(v - __half2float(hh));
}

// combined prep: blocks [0,4096) -> x split; [4096, 32768) -> weights
__global__ void prep_kernel(const float* __restrict__ x,
                            const float* __restrict__ weight,
                            const float* __restrict__ w_right,
                            const float* __restrict__ w_left) {
    if (blockIdx.x == 0 && threadIdx.x == 0) { g_cnt_xr = 0; g_cnt_bil = 0; }
    int bx = blockIdx.x;
    if (bx < 4096) {
        int idx = bx * 256 + threadIdx.x;
        const float4* x4 = (const float4*)x;
        float4 a = x4[idx * 2];
        float4 b = x4[idx * 2 + 1];
        float v[8] = {a.x, a.y, a.z, a.w, b.x, b.y, b.z, b.w};
#pragma unroll
        for (int i = 0; i < 8; i++) {
            __half h, l;
            hsplit(v[i], &h, &l);
            g_XTh[(size_t)i * PLANE + idx] = h;
            g_XTl[(size_t)i * PLANE + idx] = l;
        }
    } else {
        int idx = (bx - 4096) * 256 + threadIdx.x;
        if (idx < WBTOT) {
            int kb = idx >> 18, rem = idx & (WSLICE - 1);
            int m = rem >> 9, n = rem & 511;
            float v = weight[(size_t)(m * 512 + n) * 20 + c_porder[kb]];
            size_t d = (size_t)c_kb_base[kb] + (size_t)m * c_kb_K[kb] + n;
            g_WB[d] = __float2half_rn(v);
        } else if (idx < WBTOT + 4 * WSLICE) {
            int tt = idx - WBTOT;
            int g = tt >> 18, rem = tt & (WSLICE - 1);
            int m = rem >> 9, n = rem & 511;
            g_WR[(size_t)g * WSLICE + m * 512 + n] =
                __float2half_rn(w_right[(size_t)(m * 512 + n) * 4 + g]);
        } else {
            int tt = idx - WBTOT - 4 * WSLICE;
            int g = tt >> 18, rem = tt & (WSLICE - 1);
            int m = rem >> 9, n = rem & 511;
            g_WL[(size_t)g * WSLICE + m * 512 + n] =
                __float2half_rn(w_left[(size_t)(m * 512 + n) * 4 + g]);
        }
    }
}

// pairwise qfill: thread handles 2 consecutive n; half2 loads/stores.
#define QW2(off, EXPR)                                                        \
    do {                                                                      \
        float v0, v1;                                                         \
        { const float* x_ = xa0; const float* r_ = ra0; v0 = (EXPR); }        \
        { const float* x_ = xa1; const float* r_ = ra1; v1 = (EXPR); }        \
        *(__half2*)&g_Q[(off)] = __floats2half2_rn(v0, v1);                   \
    } while (0)

__global__ void qfill_kernel(const float* __restrict__ norm_a) {
    int p = blockIdx.x * 256 + threadIdx.x;
    int base = p * 2;
    int b = base >> 9, n0 = base & 511;

    float xa0[8], xa1[8], ra0[8], ra1[8];
#pragma unroll
    for (int i = 0; i < 8; i++) {
        __half2 h = *(const __half2*)&g_XTh[(size_t)i * PLANE + base];
        __half2 l = *(const __half2*)&g_XTl[(size_t)i * PLANE + base];
        float2 hf = __half22float2(h), lf = __half22float2(l);
        xa0[i] = hf.x + lf.x;
        xa1[i] = hf.y + lf.y;
        float2 rv = *(const float2*)&g_XR[(size_t)i * PLANE + base];
        ra0[i] = rv.x;
        ra1[i] = rv.y;
    }

    // gating per element
#pragma unroll
    for (int e = 0; e < 2; e++) {
        float* r = e ? ra1 : ra0;
        int n = n0 + e;
        float nn[4];
        nn[0] = sqrtf(r[0] * r[0]);
        nn[1] = sqrtf(r[1] * r[1] + r[2] * r[2] + r[3] * r[3]);
        nn[2] = sqrtf(r[4] * r[4] + r[5] * r[5] + r[6] * r[6]);
        nn[3] = sqrtf(r[7] * r[7]);
#pragma unroll
        for (int gg = 0; gg < 4; gg++) {
            float a = norm_a[n * 4 + gg];
            float sg = 1.0f / (1.0f + expf(-a));
            float f = sg * (nn[gg] - 1.0f) + 1.0f + 1e-6f;
            float inv = 1.0f / f;
            if (gg == 0) r[0] *= inv;
            else if (gg == 1) { r[1] *= inv; r[2] *= inv; r[3] *= inv; }
            else if (gg == 2) { r[4] *= inv; r[5] *= inv; r[6] *= inv; }
            else r[7] *= inv;
        }
    }

    {
        size_t q = QOFF0 + (size_t)b * 2048 + n0;
        QW2(q,        x_[0] * r_[0]);
        QW2(q + 512,  x_[1] * r_[1] + x_[2] * r_[2] + x_[3] * r_[3]);
        QW2(q + 1024, -(x_[4] * r_[4] + x_[5] * r_[5] + x_[6] * r_[6]));
        QW2(q + 1536, -(x_[7] * r_[7]));
    }
    {
        size_t q = QOFF1 + (size_t)(b * 3) * 3072 + n0;
        QW2(q + 0,    x_[0] * r_[1]);
        QW2(q + 512,  x_[1] * r_[0]);
        QW2(q + 1024, -x_[2] * r_[4] - x_[3] * r_[5]);
        QW2(q + 1536, x_[4] * r_[2] + x_[5] * r_[3]);
        QW2(q + 2048, -x_[6] * r_[7]);
        QW2(q + 2560, -x_[7] * r_[6]);
        QW2(q + 3072 + 0,    x_[0] * r_[2]);
        QW2(q + 3072 + 512,  x_[2] * r_[0]);
        QW2(q + 3072 + 1024, x_[1] * r_[4] - x_[3] * r_[6]);
        QW2(q + 3072 + 1536, -x_[4] * r_[1] + x_[6] * r_[3]);
        QW2(q + 3072 + 2048, x_[5] * r_[7]);
        QW2(q + 3072 + 2560, x_[7] * r_[5]);
        QW2(q + 6144 + 0,    x_[0] * r_[3]);
        QW2(q + 6144 + 512,  x_[3] * r_[0]);
        QW2(q + 6144 + 1024, x_[1] * r_[5] + x_[2] * r_[6]);
        QW2(q + 6144 + 1536, -x_[5] * r_[1] - x_[6] * r_[2]);
        QW2(q + 6144 + 2048, -x_[4] * r_[7]);
        QW2(q + 6144 + 2560, -x_[7] * r_[4]);
    }
    {
        size_t q = QOFF2 + (size_t)(b * 3) * 3072 + n0;
        QW2(q + 0,    x_[0] * r_[4]);
        QW2(q + 512,  x_[1] * r_[2] - x_[2] * r_[1]);
        QW2(q + 1024, x_[3] * r_[7]);
        QW2(q + 1536, x_[4] * r_[0]);
        QW2(q + 2048, -x_[5] * r_[6] + x_[6] * r_[5]);
        QW2(q + 2560, x_[7] * r_[3]);
        QW2(q + 3072 + 0,    x_[0] * r_[5]);
        QW2(q + 3072 + 512,  x_[1] * r_[3] - x_[3] * r_[1]);
        QW2(q + 3072 + 1024, -x_[2] * r_[7]);
        QW2(q + 3072 + 1536, x_[5] * r_[0]);
        QW2(q + 3072 + 2048, x_[4] * r_[6] - x_[6] * r_[4]);
        QW2(q + 3072 + 2560, -x_[7] * r_[2]);
        QW2(q + 6144 + 0,    x_[0] * r_[6]);
        QW2(q + 6144 + 512,  x_[2] * r_[3] - x_[3] * r_[2]);
        QW2(q + 6144 + 1024, x_[1] * r_[7]);
        QW2(q + 6144 + 1536, x_[6] * r_[0]);
        QW2(q + 6144 + 2048, -x_[4] * r_[5] + x_[5] * r_[4]);
        QW2(q + 6144 + 2560, x_[7] * r_[1]);
    }
    {
        size_t q = QOFF3 + (size_t)b * 2048 + n0;
        QW2(q,        x_[0] * r_[7]);
        QW2(q + 512,  x_[1] * r_[6] - x_[2] * r_[5] + x_[3] * r_[4]);
        QW2(q + 1024, x_[4] * r_[3] - x_[5] * r_[2] + x_[6] * r_[1]);
        QW2(q + 1536, x_[7] * r_[0]);
    }
}

__global__ void merge_out_kernel(float* __restrict__ out) {
    int idx = blockIdx.x * 256 + threadIdx.x;
    const float sc = 0.70710678118654752440f;
    float4 lo, hi;
    lo.x = g_OUT8[0 * PLANE + idx] * sc;
    lo.y = g_OUT8[1 * PLANE + idx] * sc;
    lo.z = g_OUT8[2 * PLANE + idx] * sc;
    lo.w = g_OUT8[3 * PLANE + idx] * sc;
    hi.x = g_OUT8[4 * PLANE + idx] * sc;
    hi.y = g_OUT8[5 * PLANE + idx] * sc;
    hi.z = g_OUT8[6 * PLANE + idx] * sc;
    hi.w = g_OUT8[7 * PLANE + idx] * sc;
    float4* o4 = (float4*)out;
    o4[idx * 2]     = lo;
    o4[idx * 2 + 1] = hi;
}

// ---------------------------------------------------------------------------
extern "C" void kernel_launch(void* const* d_in, const int* in_sizes, int n_in,
                              void* d_out, int out_size) {
    const float* x       = (const float*)d_in[0];
    const float* weight  = (const float*)d_in[1];
    const float* w_right = (const float*)d_in[2];
    const float* w_left  = (const float*)d_in[3];
    const float* b_left  = (const float*)d_in[4];
    const float* norm_a  = (const float*)d_in[5];
    float* out = (float*)d_out;

    cudaFuncSetAttribute(gemm_xr,  cudaFuncAttributeMaxDynamicSharedMemorySize, GSMEM);
    cudaFuncSetAttribute(gemm_bil, cudaFuncAttributeMaxDynamicSharedMemorySize, GSMEM);

    prep_kernel<<<32768, 256>>>(x, weight, w_right, w_left);   // + counter reset
    gemm_xr<<<NSM2, 256, GSMEM>>>();                           // XR, persistent
    qfill_kernel<<<PLANE / 512, 256>>>(norm_a);                // gate + Q (fp16)
    gemm_bil<<<NSM2, 256, GSMEM>>>(b_left);                    // bilinear + left
    merge_out_kernel<<<PLANE / 256, 256>>>(out);
}